// round 15
// baseline (speedup 1.0000x reference)
#include <cuda_runtime.h>
#include <cuda_fp16.h>
#include <math.h>
#include <cstdint>

// ---------------- problem constants ----------------
#define BGR   10000          // graphs
#define NN    5              // nodes/graph
#define NFR   8              // frames
#define NH    (BGR*NN)       // 50000
#define RTOT  (NFR*NH)       // 400000 expanded rows
#define HID   96
#define EPG   20             // edges per graph
#define NL    4
#define EGPB  16             // graphs per edge block
#define PK    104            // smem pitch in halfs (conflict-free)

// ---------------- device scratch ----------------
__device__ float g_X [RTOT*HID];
__device__ float g_A [RTOT*HID];
__device__ float g_PR[RTOT*HID];
__device__ float g_PC[RTOT*HID];
__device__ float g_V [BGR*9];
__device__ float g_cen[BGR*3];

__device__ __forceinline__ float sgn(int o, int j) {
    return ((o >> (2 - j)) & 1) ? -1.f : 1.f;
}
// silu via single-MUFU tanh: x*sigmoid(x) = 0.5x + 0.5x*tanh(x/2)
__device__ __forceinline__ float silu(float v) {
    float h = 0.5f * v;
    float t;
    asm("tanh.approx.f32 %0, %1;" : "=f"(t) : "f"(h));
    return fmaf(h, t, h);
}
__device__ __forceinline__ uint32_t packh2(float x0, float x1) {
    uint32_t r;
    asm("cvt.rn.f16x2.f32 %0, %1, %2;" : "=r"(r) : "f"(x1), "f"(x0));
    return r;
}
__device__ __forceinline__ void split4(float4 v, uint2& hi, uint2& lo) {
    uint32_t h01 = packh2(v.x, v.y);
    uint32_t h23 = packh2(v.z, v.w);
    __half2 a = *(__half2*)&h01, b = *(__half2*)&h23;
    float2 fa = __half22float2(a), fb = __half22float2(b);
    lo.x = packh2(v.x - fa.x, v.y - fa.y);
    lo.y = packh2(v.z - fb.x, v.w - fb.y);
    hi.x = h01; hi.y = h23;
}
__device__ __forceinline__ void split2(float v0, float v1, uint32_t& hi, uint32_t& lo) {
    hi = packh2(v0, v1);
    __half2 a = *(__half2*)&hi;
    float2 f = __half22float2(a);
    lo = packh2(v0 - f.x, v1 - f.y);
}
__device__ __forceinline__ void mma16(float* c, const uint32_t* a, uint32_t b0, uint32_t b1) {
    asm volatile(
        "mma.sync.aligned.m16n8k16.row.col.f32.f16.f16.f32 "
        "{%0,%1,%2,%3}, {%4,%5,%6,%7}, {%8,%9}, {%0,%1,%2,%3};"
        : "+f"(c[0]), "+f"(c[1]), "+f"(c[2]), "+f"(c[3])
        : "r"(a[0]), "r"(a[1]), "r"(a[2]), "r"(a[3]), "r"(b0), "r"(b1));
}
__device__ __forceinline__ void ldmx4(uint32_t* r, uint32_t addr) {
    asm volatile("ldmatrix.sync.aligned.m8n8.x4.shared.b16 {%0,%1,%2,%3}, [%4];"
                 : "=r"(r[0]), "=r"(r[1]), "=r"(r[2]), "=r"(r[3]) : "r"(addr));
}
__device__ __forceinline__ uint32_t smem_u32(const void* p) {
    return (uint32_t)__cvta_generic_to_shared(p);
}

// fp16 2-split mainloop over K=96. Warp tile = 32M x 48N (wm rows, wn in {0,1}).
__device__ __forceinline__ void mma_mainloop(uint32_t AhS, uint32_t AlS,
                                             uint32_t BhS, uint32_t BlS,
                                             int wm, int wn, int lane,
                                             float acc[2][6][4]) {
    int aRow = lane & 15, aK = (lane >> 4) * 8;
    int bRow = lane & 7,  bK = ((lane >> 3) & 1) * 8;
    uint32_t bPlane = (lane >= 16) ? BlS : BhS;
    #pragma unroll
    for (int kt = 0; kt < 6; kt++) {
        int k0 = kt*16;
        uint32_t ah[2][4], al[2][4];
        #pragma unroll
        for (int mt = 0; mt < 2; mt++) {
            int rb = wm*32 + mt*16 + aRow;
            uint32_t off = (uint32_t)((rb*PK + aK + k0)*2);
            ldmx4(ah[mt], AhS + off);
            ldmx4(al[mt], AlS + off);
        }
        #pragma unroll
        for (int nt = 0; nt < 6; nt++) {
            int n0 = wn*48 + nt*8;
            uint32_t b4[4];
            ldmx4(b4, bPlane + (uint32_t)(((n0 + bRow)*PK + bK + k0)*2));
            #pragma unroll
            for (int mt = 0; mt < 2; mt++) {
                mma16(acc[mt][nt], ah[mt], b4[0], b4[1]);
                mma16(acc[mt][nt], ah[mt], b4[2], b4[3]);
                mma16(acc[mt][nt], al[mt], b4[0], b4[1]);
            }
        }
    }
}

// ---------------- 3x3 symmetric eigh (double, ascending columns) ----------------
__device__ inline void cross3d(const double* a, const double* b, double* c) {
    c[0] = a[1]*b[2] - a[2]*b[1];
    c[1] = a[2]*b[0] - a[0]*b[2];
    c[2] = a[0]*b[1] - a[1]*b[0];
}
__device__ inline void eigvec3(double a00,double a01,double a02,double a11,double a12,double a22,
                               double lam, double* v) {
    double r0[3] = {a00-lam, a01, a02};
    double r1[3] = {a01, a11-lam, a12};
    double r2[3] = {a02, a12, a22-lam};
    double c0[3], c1[3], c2[3];
    cross3d(r0, r1, c0); cross3d(r0, r2, c1); cross3d(r1, r2, c2);
    double n0 = c0[0]*c0[0]+c0[1]*c0[1]+c0[2]*c0[2];
    double n1 = c1[0]*c1[0]+c1[1]*c1[1]+c1[2]*c1[2];
    double n2 = c2[0]*c2[0]+c2[1]*c2[1]+c2[2]*c2[2];
    double* best = c0; double nb = n0;
    if (n1 > nb) { best = c1; nb = n1; }
    if (n2 > nb) { best = c2; nb = n2; }
    if (nb < 1e-300) { v[0]=1.0; v[1]=0.0; v[2]=0.0; return; }
    double inv = 1.0 / sqrt(nb);
    v[0] = best[0]*inv; v[1] = best[1]*inv; v[2] = best[2]*inv;
}
__device__ inline void eigh3(double a00,double a01,double a02,double a11,double a12,double a22,
                             float* V) {
    double p1 = a01*a01 + a02*a02 + a12*a12;
    double q  = (a00 + a11 + a22) / 3.0;
    double b00 = a00-q, b11 = a11-q, b22 = a22-q;
    double p2 = b00*b00 + b11*b11 + b22*b22 + 2.0*p1;
    if (p2 < 1e-60) {
        V[0]=1.f;V[1]=0.f;V[2]=0.f; V[3]=0.f;V[4]=1.f;V[5]=0.f; V[6]=0.f;V[7]=0.f;V[8]=1.f;
        return;
    }
    double p = sqrt(p2 / 6.0);
    double inv = 1.0 / p;
    double c00=b00*inv, c01=a01*inv, c02=a02*inv, c11=b11*inv, c12=a12*inv, c22=b22*inv;
    double det = c00*(c11*c22 - c12*c12) - c01*(c01*c22 - c12*c02) + c02*(c01*c12 - c11*c02);
    double r = 0.5 * det;
    r = fmin(1.0, fmax(-1.0, r));
    double phi  = acos(r) / 3.0;
    double lmax = q + 2.0*p*cos(phi);
    double lmin = q + 2.0*p*cos(phi + 2.0943951023931953);
    double vmin[3], vmax[3], vmid[3];
    eigvec3(a00,a01,a02,a11,a12,a22, lmin, vmin);
    eigvec3(a00,a01,a02,a11,a12,a22, lmax, vmax);
    cross3d(vmax, vmin, vmid);
    double nm = sqrt(vmid[0]*vmid[0]+vmid[1]*vmid[1]+vmid[2]*vmid[2]);
    double invm = (nm > 1e-300) ? 1.0/nm : 0.0;
    vmid[0]*=invm; vmid[1]*=invm; vmid[2]*=invm;
    V[0]=(float)vmin[0]; V[3]=(float)vmin[1]; V[6]=(float)vmin[2];
    V[1]=(float)vmid[0]; V[4]=(float)vmid[1]; V[7]=(float)vmid[2];
    V[2]=(float)vmax[0]; V[5]=(float)vmax[1]; V[8]=(float)vmax[2];
}

// ---------------- kernel: initial frames + out init (1 thread / graph) ----------------
__global__ void frame_kernel(const float* __restrict__ h, float* __restrict__ out) {
    int b = blockIdx.x * blockDim.x + threadIdx.x;
    if (b >= BGR) return;
    const float* hp = h + (size_t)(b*NN)*6;
    double P[NN][3];
    double c0=0, c1=0, c2=0;
    for (int p = 0; p < NN; p++) {
        P[p][0] = hp[p*6+0]; P[p][1] = hp[p*6+1]; P[p][2] = hp[p*6+2];
        c0 += P[p][0]; c1 += P[p][1]; c2 += P[p][2];
    }
    c0 *= 0.2; c1 *= 0.2; c2 *= 0.2;
    double a00=0,a01=0,a02=0,a11=0,a12=0,a22=0;
    for (int p = 0; p < NN; p++) {
        double d0 = P[p][0]-c0, d1 = P[p][1]-c1, d2 = P[p][2]-c2;
        a00 += d0*d0; a01 += d0*d1; a02 += d0*d2;
        a11 += d1*d1; a12 += d1*d2; a22 += d2*d2;
    }
    float V[9];
    eigh3(a00,a01,a02,a11,a12,a22, V);
    for (int i = 0; i < 9; i++) g_V[b*9+i] = V[i];
    g_cen[b*3+0] = (float)c0; g_cen[b*3+1] = (float)c1; g_cen[b*3+2] = (float)c2;
    for (int p = 0; p < NN; p++) {
        out[(size_t)(b*NN + p)*3 + 0] = (float)c0;
        out[(size_t)(b*NN + p)*3 + 1] = (float)c1;
        out[(size_t)(b*NN + p)*3 + 2] = (float)c2;
    }
}

// ---------------- kernel: frame transform + embedding (block = graph-frame) ----------------
__global__ __launch_bounds__(96) void embed_kernel(const float* __restrict__ h,
                                                   const float* __restrict__ Wg,
                                                   const float* __restrict__ bg) {
    int u = blockIdx.x;
    int g = u >> 3, o = u & 7;
    __shared__ float in6[NN][6];
    __shared__ float Vs[9];
    __shared__ float cen[3];
    int tid = threadIdx.x;
    if (tid < 9)  Vs[tid] = g_V[g*9+tid];
    if (tid >= 9 && tid < 12) cen[tid-9] = g_cen[g*3 + tid - 9];
    __syncthreads();
    if (tid < 30) {
        int p = tid / 6, k = tid - p*6;
        int i = k % 3; bool vel = (k >= 3);
        const float* hp = &h[(size_t)(g*NN + p)*6];
        float x0, x1, x2;
        if (vel) { x0 = hp[3]; x1 = hp[4]; x2 = hp[5]; }
        else     { x0 = hp[0]-cen[0]; x1 = hp[1]-cen[1]; x2 = hp[2]-cen[2]; }
        float val = Vs[0*3+i]*x0 + Vs[1*3+i]*x1 + Vs[2*3+i]*x2;
        in6[p][k] = sgn(o, i) * val;
    }
    __syncthreads();
    int j = tid;
    float bv = bg[j];
    for (int p = 0; p < NN; p++) {
        float s = bv;
        #pragma unroll
        for (int k = 0; k < 6; k++) s += in6[p][k] * Wg[k*96 + j];
        g_X[(size_t)(o*NH + g*NN + p)*HID + j] = s;
    }
}

// ---------------- tensor dense GEMM (single / dual weight), 256 threads ----------------
#define TD_SMEM ((128*PK*2 + 96*PK*2)*2)   // 93184 bytes
#define TD_BFILL(WSRC)                                                     \
    _Pragma("unroll")                                                      \
    for (int i = 0; i < 36; i++) {                                         \
        int idx = tid + i*256;                                             \
        int k = idx / 96, n = idx - k*96;                                  \
        float w = (WSRC)[idx];                                             \
        __half hv = __float2half_rn(w);                                    \
        float lv = w - __half2float(hv);                                   \
        Bh[n*PK + k] = hv;                                                 \
        Bl[n*PK + k] = __float2half_rn(lv);                                \
    }
#define TD_AFILL(INSRC)                                                    \
    _Pragma("unroll")                                                      \
    for (int i = 0; i < 12; i++) {                                         \
        int idx = tid + i*256;                                             \
        int r = idx / 24, q = idx - r*24;                                  \
        float4 v = *(const float4*)&(INSRC)[(size_t)(row0 + r)*96 + q*4];  \
        uint2 hi, lo;                                                      \
        split4(v, hi, lo);                                                 \
        *(uint2*)&Ah[r*PK + q*4] = hi;                                     \
        *(uint2*)&Al[r*PK + q*4] = lo;                                     \
    }
#define ACC_ZERO()                                                         \
    _Pragma("unroll")                                                      \
    for (int mt = 0; mt < 2; mt++)                                         \
        _Pragma("unroll")                                                  \
        for (int nt = 0; nt < 6; nt++)                                     \
            _Pragma("unroll")                                              \
            for (int e = 0; e < 4; e++) acc[mt][nt][e] = 0.f;

__global__ __launch_bounds__(256, 2) void tdense_k(const float* __restrict__ INa,
                                                   const float* __restrict__ INb,
                                                   const float* __restrict__ W,
                                                   const float* __restrict__ bias,
                                                   float* __restrict__ OUT,
                                                   int nhalves, int dosilu,
                                                   const float* __restrict__ W2p,
                                                   float* __restrict__ OUT2) {
    extern __shared__ __half smh[];
    __half* Ah = smh;
    __half* Al = Ah + 128*PK;
    __half* Bh = Al + 128*PK;
    __half* Bl = Bh + 96*PK;
    uint32_t AhS = smem_u32(Ah), AlS = smem_u32(Al), BhS = smem_u32(Bh), BlS = smem_u32(Bl);
    int tid = threadIdx.x;
    int warp = tid >> 5, lane = tid & 31;
    int gid = lane >> 2, tig = lane & 3;
    int wm = warp >> 1, wn = warp & 1;
    int row0 = blockIdx.x * 128;

    float acc[2][6][4];
    ACC_ZERO()
    for (int hh = 0; hh < nhalves; hh++) {
        const float* IN = hh ? INb : INa;
        const float* Wh = W + hh*96*96;
        TD_AFILL(IN)
        TD_BFILL(Wh)
        __syncthreads();
        mma_mainloop(AhS, AlS, BhS, BlS, wm, wn, lane, acc);
        __syncthreads();
    }
    // second-weight B fill hoisted above epilogue (B planes dead after mainloop;
    // LDG latency overlaps epilogue math + stores)
    if (W2p) { TD_BFILL(W2p) }
    #pragma unroll
    for (int nt = 0; nt < 6; nt++) {
        int col = wn*48 + nt*8 + tig*2;
        float2 b2 = bias ? *(const float2*)&bias[col] : make_float2(0.f, 0.f);
        #pragma unroll
        for (int mt = 0; mt < 2; mt++) {
            size_t r0w = (size_t)(row0 + wm*32 + mt*16 + gid);
            float v0 = acc[mt][nt][0] + b2.x, v1 = acc[mt][nt][1] + b2.y;
            float v2 = acc[mt][nt][2] + b2.x, v3 = acc[mt][nt][3] + b2.y;
            if (dosilu) { v0 = silu(v0); v1 = silu(v1); v2 = silu(v2); v3 = silu(v3); }
            *(float2*)&OUT[r0w*96 + col]       = make_float2(v0, v1);
            *(float2*)&OUT[(r0w + 8)*96 + col] = make_float2(v2, v3);
        }
    }
    if (W2p) {
        __syncthreads();
        ACC_ZERO()
        mma_mainloop(AhS, AlS, BhS, BlS, wm, wn, lane, acc);
        #pragma unroll
        for (int nt = 0; nt < 6; nt++) {
            int col = wn*48 + nt*8 + tig*2;
            #pragma unroll
            for (int mt = 0; mt < 2; mt++) {
                size_t r0w = (size_t)(row0 + wm*32 + mt*16 + gid);
                *(float2*)&OUT2[r0w*96 + col]       = make_float2(acc[mt][nt][0], acc[mt][nt][1]);
                *(float2*)&OUT2[(r0w + 8)*96 + col] = make_float2(acc[mt][nt][2], acc[mt][nt][3]);
            }
        }
    }
}

// ---------------- fused node MLP: X = (silu(cat[X,A]@nw1+b1)) @ nw2 + b2 ----------------
__global__ __launch_bounds__(256, 2) void tnode_k(const float* __restrict__ Xin,
                                                  const float* __restrict__ Ain,
                                                  const float* __restrict__ W1,
                                                  const float* __restrict__ b1,
                                                  const float* __restrict__ W2,
                                                  const float* __restrict__ b2g,
                                                  float* __restrict__ Xout) {
    extern __shared__ __half smh[];
    __half* Ah = smh;
    __half* Al = Ah + 128*PK;
    __half* Bh = Al + 128*PK;
    __half* Bl = Bh + 96*PK;
    uint32_t AhS = smem_u32(Ah), AlS = smem_u32(Al), BhS = smem_u32(Bh), BlS = smem_u32(Bl);
    int tid = threadIdx.x;
    int warp = tid >> 5, lane = tid & 31;
    int gid = lane >> 2, tig = lane & 3;
    int wm = warp >> 1, wn = warp & 1;
    int row0 = blockIdx.x * 128;

    float acc[2][6][4];
    ACC_ZERO()
    for (int hh = 0; hh < 2; hh++) {
        const float* IN = hh ? Ain : Xin;
        const float* Wh = W1 + hh*96*96;
        TD_AFILL(IN)
        TD_BFILL(Wh)
        __syncthreads();
        mma_mainloop(AhS, AlS, BhS, BlS, wm, wn, lane, acc);
        __syncthreads();
    }
    // hoist W2 fill above the T-epilogue (B planes dead; overlaps LDG latency)
    TD_BFILL(W2)
    // T = silu(acc + b1) -> write into A planes (consumed by second GEMM)
    #pragma unroll
    for (int nt = 0; nt < 6; nt++) {
        int col = wn*48 + nt*8 + tig*2;
        float2 bb = *(const float2*)&b1[col];
        #pragma unroll
        for (int mt = 0; mt < 2; mt++) {
            int r = wm*32 + mt*16 + gid;
            float v0 = silu(acc[mt][nt][0] + bb.x), v1 = silu(acc[mt][nt][1] + bb.y);
            float v2 = silu(acc[mt][nt][2] + bb.x), v3 = silu(acc[mt][nt][3] + bb.y);
            uint32_t hi, lo;
            split2(v0, v1, hi, lo);
            *(uint32_t*)&Ah[r*PK + col] = hi;
            *(uint32_t*)&Al[r*PK + col] = lo;
            split2(v2, v3, hi, lo);
            *(uint32_t*)&Ah[(r+8)*PK + col] = hi;
            *(uint32_t*)&Al[(r+8)*PK + col] = lo;
        }
    }
    __syncthreads();
    ACC_ZERO()
    mma_mainloop(AhS, AlS, BhS, BlS, wm, wn, lane, acc);
    #pragma unroll
    for (int nt = 0; nt < 6; nt++) {
        int col = wn*48 + nt*8 + tig*2;
        float2 bb = *(const float2*)&b2g[col];
        #pragma unroll
        for (int mt = 0; mt < 2; mt++) {
            size_t r0w = (size_t)(row0 + wm*32 + mt*16 + gid);
            *(float2*)&Xout[r0w*96 + col] =
                make_float2(acc[mt][nt][0] + bb.x, acc[mt][nt][1] + bb.y);
            *(float2*)&Xout[(r0w + 8)*96 + col] =
                make_float2(acc[mt][nt][2] + bb.x, acc[mt][nt][3] + bb.y);
        }
    }
}

// ---------------- fused final: T = silu(X@dw1+db1) in smem; out += frame-mean decode ----------------
__global__ __launch_bounds__(256, 2) void tfinal_k(const float* __restrict__ Xin,
                                                   const float* __restrict__ W1,
                                                   const float* __restrict__ b1,
                                                   const float* __restrict__ dw2,
                                                   const float* __restrict__ db2,
                                                   float* __restrict__ out) {
    extern __shared__ __half smh[];
    __half* Ah = smh;
    __half* Al = Ah + 128*PK;
    __half* Bh = Al + 128*PK;
    __half* Bl = Bh + 96*PK;
    float*  Tsm = (float*)smh;           // [128][97] fp32, reuses A-plane region after GEMM
    uint32_t AhS = smem_u32(Ah), AlS = smem_u32(Al), BhS = smem_u32(Bh), BlS = smem_u32(Bl);
    __shared__ float dw2s[96*3];
    __shared__ float db2s[3];
    int tid = threadIdx.x;
    int warp = tid >> 5, lane = tid & 31;
    int gid = lane >> 2, tig = lane & 3;
    int wm = warp >> 1, wn = warp & 1;
    int row0 = blockIdx.x * 128;

    for (int i = tid; i < 96*3; i += 256) dw2s[i] = dw2[i];
    if (tid < 3) db2s[tid] = db2[tid];

    float acc[2][6][4];
    ACC_ZERO()
    TD_AFILL(Xin)
    TD_BFILL(W1)
    __syncthreads();
    mma_mainloop(AhS, AlS, BhS, BlS, wm, wn, lane, acc);
    __syncthreads();   // everyone done with A planes -> Tsm may overwrite
    #pragma unroll
    for (int nt = 0; nt < 6; nt++) {
        int col = wn*48 + nt*8 + tig*2;
        float2 bb = *(const float2*)&b1[col];
        #pragma unroll
        for (int mt = 0; mt < 2; mt++) {
            int r = wm*32 + mt*16 + gid;
            Tsm[r*97 + col]     = silu(acc[mt][nt][0] + bb.x);
            Tsm[r*97 + col + 1] = silu(acc[mt][nt][1] + bb.y);
            Tsm[(r+8)*97 + col]     = silu(acc[mt][nt][2] + bb.x);
            Tsm[(r+8)*97 + col + 1] = silu(acc[mt][nt][3] + bb.y);
        }
    }
    __syncthreads();
    if (tid < 128) {
        int grow = row0 + tid;
        int o = grow / NH;
        int node = grow - o*NH;
        int b = node / NN;
        const float* Tr = &Tsm[tid*97];
        float q0 = db2s[0], q1 = db2s[1], q2 = db2s[2];
        #pragma unroll 8
        for (int k = 0; k < 96; k++) {
            float t = Tr[k];
            q0 += t * dw2s[k*3+0];
            q1 += t * dw2s[k*3+1];
            q2 += t * dw2s[k*3+2];
        }
        float s0 = sgn(o,0)*q0, s1 = sgn(o,1)*q1, s2 = sgn(o,2)*q2;
        const float* V = &g_V[b*9];
        float v0 = V[0]*s0 + V[1]*s1 + V[2]*s2;
        float v1 = V[3]*s0 + V[4]*s1 + V[5]*s2;
        float v2 = V[6]*s0 + V[7]*s1 + V[8]*s2;
        atomicAdd(&out[(size_t)node*3 + 0], 0.125f*v0);
        atomicAdd(&out[(size_t)node*3 + 1], 0.125f*v1);
        atomicAdd(&out[(size_t)node*3 + 2], 0.125f*v2);
    }
}

// ---------------- edge kernel: EGPB graphs/block, 320 threads (10 warps: 5M x 2N) ----------------
#define EDGE_SMEM ((160*PK*2 + 96*PK*2)*2 + (192 + 96 + 2*EPG)*4)
__global__ __launch_bounds__(320, 2) void edge_k(const float* __restrict__ ea,
                                                 const float* __restrict__ Wea,
                                                 const float* __restrict__ eb1,
                                                 const float* __restrict__ W2,
                                                 const float* __restrict__ eb2) {
    extern __shared__ __half smh[];
    __half* M1h = smh;                    // [160][PK]
    __half* M1l = M1h + 160*PK;
    __half* Bh  = M1l + 160*PK;           // [96][PK]
    __half* Bl  = Bh + 96*PK;
    float*  Weas = (float*)(Bl + 96*PK);  // [192]
    float*  eb1s = Weas + 192;            // [96]
    float*  eas  = eb1s + 96;             // [40]
    uint32_t M1hS = smem_u32(M1h), M1lS = smem_u32(M1l);
    uint32_t BhS  = smem_u32(Bh),  BlS  = smem_u32(Bl);
    int tid = threadIdx.x;
    int warp = tid >> 5, lane = tid & 31;
    int gid = lane >> 2, tig = lane & 3;
    int wm = warp >> 1, wn = warp & 1;    // wm 0..4, wn 0..1

    for (int idx = tid; idx < 96*96; idx += 320) {
        int k = idx / 96, n = idx - k*96;
        float w = W2[idx];
        __half hv = __float2half_rn(w);
        float lv = w - __half2float(hv);
        Bh[n*PK + k] = hv;
        Bl[n*PK + k] = __float2half_rn(lv);
    }
    if (tid < 192) Weas[tid] = Wea[tid];
    if (tid >= 192 && tid < 288) eb1s[tid-192] = eb1[tid-192];
    if (tid >= 288 && tid < 288 + 2*EPG)
        eas[tid-288] = ea[(size_t)blockIdx.x*EGPB*EPG*2 + tid - 288];
    __syncthreads();

    for (int gg = 0; gg < EGPB; gg++) {
        int g = blockIdx.x * EGPB + gg;
        // m1 fill: 960 units (40 source-groups x 24 k-quads), 3 per thread
        #pragma unroll
        for (int t = 0; t < 3; t++) {
            int unit = tid + t*320;
            int m = unit / 24, q = unit - m*24;
            int u = m / 5, rr = m - u*5;
            size_t nb = (size_t)(u*NH + g*NN);
            float4 pr = *(const float4*)&g_PR[(nb+rr)*96 + q*4];
            float4 wa = *(const float4*)&Weas[q*4];
            float4 wb = *(const float4*)&Weas[96 + q*4];
            float4 be = *(const float4*)&eb1s[q*4];
            #pragma unroll
            for (int e = 0; e < 4; e++) {
                int c = e + (e >= rr);
                int le = rr*4 + e;
                float a0 = eas[le*2], a1 = eas[le*2+1];
                float4 pc = *(const float4*)&g_PC[(nb+c)*96 + q*4];
                float4 v;
                v.x = silu(pr.x + pc.x + a0*wa.x + a1*wb.x + be.x);
                v.y = silu(pr.y + pc.y + a0*wa.y + a1*wb.y + be.y);
                v.z = silu(pr.z + pc.z + a0*wa.z + a1*wb.z + be.z);
                v.w = silu(pr.w + pc.w + a0*wa.w + a1*wb.w + be.w);
                uint2 hi, lo;
                split4(v, hi, lo);
                int row = m*4 + e;
                *(uint2*)&M1h[row*PK + q*4] = hi;
                *(uint2*)&M1l[row*PK + q*4] = lo;
            }
        }
        __syncthreads();   // M1 ready; eas reads done

        if (gg + 1 < EGPB && tid < 2*EPG)
            eas[tid] = ea[(size_t)(g+1)*EPG*2 + tid];

        float acc[2][6][4];
        ACC_ZERO()
        mma_mainloop(M1hS, M1lS, BhS, BlS, wm, wn, lane, acc);

        // epilogue: silu + shuffle-aggregate 4 rows (lanes gid^1, gid^2) -> g_A
        #pragma unroll
        for (int nt = 0; nt < 6; nt++) {
            int col = wn*48 + nt*8 + tig*2;
            float2 b2 = *(const float2*)&eb2[col];
            #pragma unroll
            for (int mt = 0; mt < 2; mt++) {
                float v0 = silu(acc[mt][nt][0] + b2.x);
                float v1 = silu(acc[mt][nt][1] + b2.y);
                float v2 = silu(acc[mt][nt][2] + b2.x);
                float v3 = silu(acc[mt][nt][3] + b2.y);
                v0 += __shfl_xor_sync(0xffffffffu, v0, 4);
                v0 += __shfl_xor_sync(0xffffffffu, v0, 8);
                v1 += __shfl_xor_sync(0xffffffffu, v1, 4);
                v1 += __shfl_xor_sync(0xffffffffu, v1, 8);
                v2 += __shfl_xor_sync(0xffffffffu, v2, 4);
                v2 += __shfl_xor_sync(0xffffffffu, v2, 8);
                v3 += __shfl_xor_sync(0xffffffffu, v3, 4);
                v3 += __shfl_xor_sync(0xffffffffu, v3, 8);
                if ((gid & 3) == 0) {
                    int mlo = (wm*32 + mt*16 + gid) >> 2;
                    int mhi = mlo + 2;
                    int ulo = mlo / 5, rlo = mlo - ulo*5;
                    int uhi = mhi / 5, rhi = mhi - uhi*5;
                    *(float2*)&g_A[(size_t)(ulo*NH + g*NN + rlo)*96 + col] = make_float2(v0, v1);
                    *(float2*)&g_A[(size_t)(uhi*NH + g*NN + rhi)*96 + col] = make_float2(v2, v3);
                }
            }
        }
        __syncthreads();
    }
}

// ---------------- relatent: invert_latent + create_latent fused (block = graph) ----------------
__global__ __launch_bounds__(160) void relatent_kernel() {
    int b = blockIdx.x;
    int tid = threadIdx.x;
    int lane = tid & 31, warp = tid >> 5;
    int p = warp, f = lane;
    __shared__ float Vs[9];
    __shared__ float Vn[9];
    __shared__ float scen[3];
    __shared__ float wred[5][6];
    if (tid < 9) Vs[tid] = g_V[b*9 + tid];
    __syncthreads();
    float pm0 = 0.f, pm1 = 0.f, pm2 = 0.f;
    #pragma unroll
    for (int o = 0; o < NFR; o++) {
        const float* xr = &g_X[(size_t)(o*NH + b*NN + p)*HID + 3*f];
        float x0 = xr[0], x1 = xr[1], x2 = xr[2];
        float y0 = sgn(o,0)*x0, y1 = sgn(o,1)*x1, y2 = sgn(o,2)*x2;
        pm0 += Vs[0]*y0 + Vs[1]*y1 + Vs[2]*y2;
        pm1 += Vs[3]*y0 + Vs[4]*y1 + Vs[5]*y2;
        pm2 += Vs[6]*y0 + Vs[7]*y1 + Vs[8]*y2;
    }
    pm0 *= 0.125f; pm1 *= 0.125f; pm2 *= 0.125f;
    float r0 = pm0, r1 = pm1, r2 = pm2;
    for (int off = 16; off; off >>= 1) {
        r0 += __shfl_down_sync(0xffffffffu, r0, off);
        r1 += __shfl_down_sync(0xffffffffu, r1, off);
        r2 += __shfl_down_sync(0xffffffffu, r2, off);
    }
    if (lane == 0) { wred[warp][0]=r0; wred[warp][1]=r1; wred[warp][2]=r2; }
    __syncthreads();
    if (tid == 0) {
        float c0=0,c1=0,c2=0;
        for (int w = 0; w < 5; w++) { c0+=wred[w][0]; c1+=wred[w][1]; c2+=wred[w][2]; }
        scen[0] = c0/160.f; scen[1] = c1/160.f; scen[2] = c2/160.f;
    }
    __syncthreads();
    float d0 = pm0 - scen[0], d1 = pm1 - scen[1], d2 = pm2 - scen[2];
    float q[6] = { d0*d0, d0*d1, d0*d2, d1*d1, d1*d2, d2*d2 };
    #pragma unroll
    for (int i = 0; i < 6; i++) {
        float v = q[i];
        for (int off = 16; off; off >>= 1) v += __shfl_down_sync(0xffffffffu, v, off);
        q[i] = v;
    }
    if (lane == 0) { for (int i = 0; i < 6; i++) wred[warp][i] = q[i]; }
    __syncthreads();
    if (tid == 0) {
        double A[6] = {0,0,0,0,0,0};
        for (int w = 0; w < 5; w++)
            for (int i = 0; i < 6; i++) A[i] += (double)wred[w][i];
        float V[9];
        eigh3(A[0],A[1],A[2],A[3],A[4],A[5], V);
        for (int i = 0; i < 9; i++) { Vn[i] = V[i]; g_V[b*9+i] = V[i]; }
    }
    __syncthreads();
    float y0 = Vn[0]*d0 + Vn[3]*d1 + Vn[6]*d2;
    float y1 = Vn[1]*d0 + Vn[4]*d1 + Vn[7]*d2;
    float y2 = Vn[2]*d0 + Vn[5]*d1 + Vn[8]*d2;
    #pragma unroll
    for (int o = 0; o < NFR; o++) {
        float* xr = &g_X[(size_t)(o*NH + b*NN + p)*HID + 3*f];
        xr[0] = sgn(o,0)*y0; xr[1] = sgn(o,1)*y1; xr[2] = sgn(o,2)*y2;
    }
}

// ---------------- host launcher ----------------
extern "C" void kernel_launch(void* const* d_in, const int* in_sizes, int n_in,
                              void* d_out, int out_size) {
    const float* h     = (const float*)d_in[0];
    const float* ea    = (const float*)d_in[1];
    const float* emb_w = (const float*)d_in[2];
    const float* emb_b = (const float*)d_in[3];
    const float* ew1   = (const float*)d_in[4];   // [4,194,96]
    const float* eb1   = (const float*)d_in[5];   // [4,96]
    const float* ew2   = (const float*)d_in[6];   // [4,96,96]
    const float* eb2   = (const float*)d_in[7];   // [4,96]
    const float* nw1   = (const float*)d_in[8];   // [4,192,96]
    const float* nb1   = (const float*)d_in[9];
    const float* nw2   = (const float*)d_in[10];  // [4,96,96]
    const float* nb2   = (const float*)d_in[11];
    const float* dw1   = (const float*)d_in[12];  // [96,96]
    const float* db1   = (const float*)d_in[13];
    const float* dw2   = (const float*)d_in[14];  // [96,3]
    const float* db2   = (const float*)d_in[15];
    float* out = (float*)d_out;

    float *X, *A, *PR, *PC;
    cudaGetSymbolAddress((void**)&X,  g_X);
    cudaGetSymbolAddress((void**)&A,  g_A);
    cudaGetSymbolAddress((void**)&PR, g_PR);
    cudaGetSymbolAddress((void**)&PC, g_PC);
    cudaFuncSetAttribute(tdense_k, cudaFuncAttributeMaxDynamicSharedMemorySize, TD_SMEM);
    cudaFuncSetAttribute(tnode_k,  cudaFuncAttributeMaxDynamicSharedMemorySize, TD_SMEM);
    cudaFuncSetAttribute(tfinal_k, cudaFuncAttributeMaxDynamicSharedMemorySize, TD_SMEM);
    cudaFuncSetAttribute(edge_k,   cudaFuncAttributeMaxDynamicSharedMemorySize, EDGE_SMEM);

    frame_kernel<<<(BGR + 127)/128, 128>>>(h, out);
    embed_kernel<<<BGR*NFR, 96>>>(h, emb_w, emb_b);

    const int TG = RTOT / 128;   // 3125 tensor-dense blocks
    for (int l = 0; l < NL; l++) {
        const float* ew1_l = ew1 + (size_t)l*194*96;
        tdense_k<<<TG, 256, TD_SMEM>>>(X, nullptr, ew1_l, nullptr, PR, 1, 0,
                                       ew1_l + 96*96, PC);
        edge_k<<<BGR/EGPB, 320, EDGE_SMEM>>>(ea, ew1_l + 192*96, eb1 + l*96,
                                             ew2 + (size_t)l*96*96, eb2 + l*96);
        tnode_k<<<TG, 256, TD_SMEM>>>(X, A, nw1 + (size_t)l*192*96, nb1 + l*96,
                                      nw2 + (size_t)l*96*96, nb2 + l*96, X);
        if (l < NL - 1) relatent_kernel<<<BGR, 160>>>();
    }
    tfinal_k<<<TG, 256, TD_SMEM>>>(X, dw1, db1, dw2, db2, out);
}

// round 16
// speedup vs baseline: 1.0500x; 1.0500x over previous
#include <cuda_runtime.h>
#include <cuda_fp16.h>
#include <math.h>
#include <cstdint>

// ---------------- problem constants ----------------
#define BGR   10000          // graphs
#define NN    5              // nodes/graph
#define NFR   8              // frames
#define NH    (BGR*NN)       // 50000
#define RTOT  (NFR*NH)       // 400000 expanded rows
#define HID   96
#define EPG   20             // edges per graph
#define NL    4
#define EGPB  8              // graphs per edge block (16 regressed: tail-wave quantum)
#define PK    104            // smem pitch in halfs (conflict-free)

// ---------------- device scratch ----------------
__device__ float g_X [RTOT*HID];
__device__ float g_A [RTOT*HID];
__device__ float g_PR[RTOT*HID];
__device__ float g_PC[RTOT*HID];
__device__ float g_V [BGR*9];
__device__ float g_cen[BGR*3];

__device__ __forceinline__ float sgn(int o, int j) {
    return ((o >> (2 - j)) & 1) ? -1.f : 1.f;
}
// silu via single-MUFU tanh: x*sigmoid(x) = 0.5x + 0.5x*tanh(x/2)
__device__ __forceinline__ float silu(float v) {
    float h = 0.5f * v;
    float t;
    asm("tanh.approx.f32 %0, %1;" : "=f"(t) : "f"(h));
    return fmaf(h, t, h);
}
__device__ __forceinline__ uint32_t packh2(float x0, float x1) {
    uint32_t r;
    asm("cvt.rn.f16x2.f32 %0, %1, %2;" : "=r"(r) : "f"(x1), "f"(x0));
    return r;
}
__device__ __forceinline__ void split4(float4 v, uint2& hi, uint2& lo) {
    uint32_t h01 = packh2(v.x, v.y);
    uint32_t h23 = packh2(v.z, v.w);
    __half2 a = *(__half2*)&h01, b = *(__half2*)&h23;
    float2 fa = __half22float2(a), fb = __half22float2(b);
    lo.x = packh2(v.x - fa.x, v.y - fa.y);
    lo.y = packh2(v.z - fb.x, v.w - fb.y);
    hi.x = h01; hi.y = h23;
}
__device__ __forceinline__ void split2(float v0, float v1, uint32_t& hi, uint32_t& lo) {
    hi = packh2(v0, v1);
    __half2 a = *(__half2*)&hi;
    float2 f = __half22float2(a);
    lo = packh2(v0 - f.x, v1 - f.y);
}
__device__ __forceinline__ void mma16(float* c, const uint32_t* a, uint32_t b0, uint32_t b1) {
    asm volatile(
        "mma.sync.aligned.m16n8k16.row.col.f32.f16.f16.f32 "
        "{%0,%1,%2,%3}, {%4,%5,%6,%7}, {%8,%9}, {%0,%1,%2,%3};"
        : "+f"(c[0]), "+f"(c[1]), "+f"(c[2]), "+f"(c[3])
        : "r"(a[0]), "r"(a[1]), "r"(a[2]), "r"(a[3]), "r"(b0), "r"(b1));
}
__device__ __forceinline__ void ldmx4(uint32_t* r, uint32_t addr) {
    asm volatile("ldmatrix.sync.aligned.m8n8.x4.shared.b16 {%0,%1,%2,%3}, [%4];"
                 : "=r"(r[0]), "=r"(r[1]), "=r"(r[2]), "=r"(r[3]) : "r"(addr));
}
__device__ __forceinline__ uint32_t smem_u32(const void* p) {
    return (uint32_t)__cvta_generic_to_shared(p);
}

// fp16 2-split mainloop over K=96. Warp tile = 32M x 48N (wm rows, wn in {0,1}).
__device__ __forceinline__ void mma_mainloop(uint32_t AhS, uint32_t AlS,
                                             uint32_t BhS, uint32_t BlS,
                                             int wm, int wn, int lane,
                                             float acc[2][6][4]) {
    int aRow = lane & 15, aK = (lane >> 4) * 8;
    int bRow = lane & 7,  bK = ((lane >> 3) & 1) * 8;
    uint32_t bPlane = (lane >= 16) ? BlS : BhS;
    #pragma unroll
    for (int kt = 0; kt < 6; kt++) {
        int k0 = kt*16;
        uint32_t ah[2][4], al[2][4];
        #pragma unroll
        for (int mt = 0; mt < 2; mt++) {
            int rb = wm*32 + mt*16 + aRow;
            uint32_t off = (uint32_t)((rb*PK + aK + k0)*2);
            ldmx4(ah[mt], AhS + off);
            ldmx4(al[mt], AlS + off);
        }
        #pragma unroll
        for (int nt = 0; nt < 6; nt++) {
            int n0 = wn*48 + nt*8;
            uint32_t b4[4];
            ldmx4(b4, bPlane + (uint32_t)(((n0 + bRow)*PK + bK + k0)*2));
            #pragma unroll
            for (int mt = 0; mt < 2; mt++) {
                mma16(acc[mt][nt], ah[mt], b4[0], b4[1]);
                mma16(acc[mt][nt], ah[mt], b4[2], b4[3]);
                mma16(acc[mt][nt], al[mt], b4[0], b4[1]);
            }
        }
    }
}

// ---------------- 3x3 symmetric eigh (double, ascending columns) ----------------
__device__ inline void cross3d(const double* a, const double* b, double* c) {
    c[0] = a[1]*b[2] - a[2]*b[1];
    c[1] = a[2]*b[0] - a[0]*b[2];
    c[2] = a[0]*b[1] - a[1]*b[0];
}
__device__ inline void eigvec3(double a00,double a01,double a02,double a11,double a12,double a22,
                               double lam, double* v) {
    double r0[3] = {a00-lam, a01, a02};
    double r1[3] = {a01, a11-lam, a12};
    double r2[3] = {a02, a12, a22-lam};
    double c0[3], c1[3], c2[3];
    cross3d(r0, r1, c0); cross3d(r0, r2, c1); cross3d(r1, r2, c2);
    double n0 = c0[0]*c0[0]+c0[1]*c0[1]+c0[2]*c0[2];
    double n1 = c1[0]*c1[0]+c1[1]*c1[1]+c1[2]*c1[2];
    double n2 = c2[0]*c2[0]+c2[1]*c2[1]+c2[2]*c2[2];
    double* best = c0; double nb = n0;
    if (n1 > nb) { best = c1; nb = n1; }
    if (n2 > nb) { best = c2; nb = n2; }
    if (nb < 1e-300) { v[0]=1.0; v[1]=0.0; v[2]=0.0; return; }
    double inv = 1.0 / sqrt(nb);
    v[0] = best[0]*inv; v[1] = best[1]*inv; v[2] = best[2]*inv;
}
__device__ inline void eigh3(double a00,double a01,double a02,double a11,double a12,double a22,
                             float* V) {
    double p1 = a01*a01 + a02*a02 + a12*a12;
    double q  = (a00 + a11 + a22) / 3.0;
    double b00 = a00-q, b11 = a11-q, b22 = a22-q;
    double p2 = b00*b00 + b11*b11 + b22*b22 + 2.0*p1;
    if (p2 < 1e-60) {
        V[0]=1.f;V[1]=0.f;V[2]=0.f; V[3]=0.f;V[4]=1.f;V[5]=0.f; V[6]=0.f;V[7]=0.f;V[8]=1.f;
        return;
    }
    double p = sqrt(p2 / 6.0);
    double inv = 1.0 / p;
    double c00=b00*inv, c01=a01*inv, c02=a02*inv, c11=b11*inv, c12=a12*inv, c22=b22*inv;
    double det = c00*(c11*c22 - c12*c12) - c01*(c01*c22 - c12*c02) + c02*(c01*c12 - c11*c02);
    double r = 0.5 * det;
    r = fmin(1.0, fmax(-1.0, r));
    double phi  = acos(r) / 3.0;
    double lmax = q + 2.0*p*cos(phi);
    double lmin = q + 2.0*p*cos(phi + 2.0943951023931953);
    double vmin[3], vmax[3], vmid[3];
    eigvec3(a00,a01,a02,a11,a12,a22, lmin, vmin);
    eigvec3(a00,a01,a02,a11,a12,a22, lmax, vmax);
    cross3d(vmax, vmin, vmid);
    double nm = sqrt(vmid[0]*vmid[0]+vmid[1]*vmid[1]+vmid[2]*vmid[2]);
    double invm = (nm > 1e-300) ? 1.0/nm : 0.0;
    vmid[0]*=invm; vmid[1]*=invm; vmid[2]*=invm;
    V[0]=(float)vmin[0]; V[3]=(float)vmin[1]; V[6]=(float)vmin[2];
    V[1]=(float)vmid[0]; V[4]=(float)vmid[1]; V[7]=(float)vmid[2];
    V[2]=(float)vmax[0]; V[5]=(float)vmax[1]; V[8]=(float)vmax[2];
}

// ---------------- kernel: initial frames + out init (1 thread / graph) ----------------
__global__ void frame_kernel(const float* __restrict__ h, float* __restrict__ out) {
    int b = blockIdx.x * blockDim.x + threadIdx.x;
    if (b >= BGR) return;
    const float* hp = h + (size_t)(b*NN)*6;
    double P[NN][3];
    double c0=0, c1=0, c2=0;
    for (int p = 0; p < NN; p++) {
        P[p][0] = hp[p*6+0]; P[p][1] = hp[p*6+1]; P[p][2] = hp[p*6+2];
        c0 += P[p][0]; c1 += P[p][1]; c2 += P[p][2];
    }
    c0 *= 0.2; c1 *= 0.2; c2 *= 0.2;
    double a00=0,a01=0,a02=0,a11=0,a12=0,a22=0;
    for (int p = 0; p < NN; p++) {
        double d0 = P[p][0]-c0, d1 = P[p][1]-c1, d2 = P[p][2]-c2;
        a00 += d0*d0; a01 += d0*d1; a02 += d0*d2;
        a11 += d1*d1; a12 += d1*d2; a22 += d2*d2;
    }
    float V[9];
    eigh3(a00,a01,a02,a11,a12,a22, V);
    for (int i = 0; i < 9; i++) g_V[b*9+i] = V[i];
    g_cen[b*3+0] = (float)c0; g_cen[b*3+1] = (float)c1; g_cen[b*3+2] = (float)c2;
    for (int p = 0; p < NN; p++) {
        out[(size_t)(b*NN + p)*3 + 0] = (float)c0;
        out[(size_t)(b*NN + p)*3 + 1] = (float)c1;
        out[(size_t)(b*NN + p)*3 + 2] = (float)c2;
    }
}

// ---------------- kernel: frame transform + embedding (block = graph-frame) ----------------
__global__ __launch_bounds__(96) void embed_kernel(const float* __restrict__ h,
                                                   const float* __restrict__ Wg,
                                                   const float* __restrict__ bg) {
    int u = blockIdx.x;
    int g = u >> 3, o = u & 7;
    __shared__ float in6[NN][6];
    __shared__ float Vs[9];
    __shared__ float cen[3];
    int tid = threadIdx.x;
    if (tid < 9)  Vs[tid] = g_V[g*9+tid];
    if (tid >= 9 && tid < 12) cen[tid-9] = g_cen[g*3 + tid - 9];
    __syncthreads();
    if (tid < 30) {
        int p = tid / 6, k = tid - p*6;
        int i = k % 3; bool vel = (k >= 3);
        const float* hp = &h[(size_t)(g*NN + p)*6];
        float x0, x1, x2;
        if (vel) { x0 = hp[3]; x1 = hp[4]; x2 = hp[5]; }
        else     { x0 = hp[0]-cen[0]; x1 = hp[1]-cen[1]; x2 = hp[2]-cen[2]; }
        float val = Vs[0*3+i]*x0 + Vs[1*3+i]*x1 + Vs[2*3+i]*x2;
        in6[p][k] = sgn(o, i) * val;
    }
    __syncthreads();
    int j = tid;
    float bv = bg[j];
    for (int p = 0; p < NN; p++) {
        float s = bv;
        #pragma unroll
        for (int k = 0; k < 6; k++) s += in6[p][k] * Wg[k*96 + j];
        g_X[(size_t)(o*NH + g*NN + p)*HID + j] = s;
    }
}

// ---------------- tensor dense GEMM (single / dual weight), 256 threads ----------------
#define TD_SMEM ((128*PK*2 + 96*PK*2)*2)   // 93184 bytes
#define TD_BFILL(WSRC)                                                     \
    _Pragma("unroll")                                                      \
    for (int i = 0; i < 36; i++) {                                         \
        int idx = tid + i*256;                                             \
        int k = idx / 96, n = idx - k*96;                                  \
        float w = (WSRC)[idx];                                             \
        __half hv = __float2half_rn(w);                                    \
        float lv = w - __half2float(hv);                                   \
        Bh[n*PK + k] = hv;                                                 \
        Bl[n*PK + k] = __float2half_rn(lv);                                \
    }
#define TD_AFILL(INSRC)                                                    \
    _Pragma("unroll")                                                      \
    for (int i = 0; i < 12; i++) {                                         \
        int idx = tid + i*256;                                             \
        int r = idx / 24, q = idx - r*24;                                  \
        float4 v = *(const float4*)&(INSRC)[(size_t)(row0 + r)*96 + q*4];  \
        uint2 hi, lo;                                                      \
        split4(v, hi, lo);                                                 \
        *(uint2*)&Ah[r*PK + q*4] = hi;                                     \
        *(uint2*)&Al[r*PK + q*4] = lo;                                     \
    }
#define ACC_ZERO()                                                         \
    _Pragma("unroll")                                                      \
    for (int mt = 0; mt < 2; mt++)                                         \
        _Pragma("unroll")                                                  \
        for (int nt = 0; nt < 6; nt++)                                     \
            _Pragma("unroll")                                              \
            for (int e = 0; e < 4; e++) acc[mt][nt][e] = 0.f;

__global__ __launch_bounds__(256, 2) void tdense_k(const float* __restrict__ INa,
                                                   const float* __restrict__ INb,
                                                   const float* __restrict__ W,
                                                   const float* __restrict__ bias,
                                                   float* __restrict__ OUT,
                                                   int nhalves, int dosilu,
                                                   const float* __restrict__ W2p,
                                                   float* __restrict__ OUT2) {
    extern __shared__ __half smh[];
    __half* Ah = smh;
    __half* Al = Ah + 128*PK;
    __half* Bh = Al + 128*PK;
    __half* Bl = Bh + 96*PK;
    uint32_t AhS = smem_u32(Ah), AlS = smem_u32(Al), BhS = smem_u32(Bh), BlS = smem_u32(Bl);
    int tid = threadIdx.x;
    int warp = tid >> 5, lane = tid & 31;
    int gid = lane >> 2, tig = lane & 3;
    int wm = warp >> 1, wn = warp & 1;
    int row0 = blockIdx.x * 128;

    float acc[2][6][4];
    ACC_ZERO()
    for (int hh = 0; hh < nhalves; hh++) {
        const float* IN = hh ? INb : INa;
        const float* Wh = W + hh*96*96;
        TD_AFILL(IN)
        TD_BFILL(Wh)
        __syncthreads();
        mma_mainloop(AhS, AlS, BhS, BlS, wm, wn, lane, acc);
        __syncthreads();
    }
    // second-weight B fill hoisted above epilogue (B planes dead after mainloop;
    // LDG latency overlaps epilogue math + stores) — measured ~40us win round 15
    if (W2p) { TD_BFILL(W2p) }
    #pragma unroll
    for (int nt = 0; nt < 6; nt++) {
        int col = wn*48 + nt*8 + tig*2;
        float2 b2 = bias ? *(const float2*)&bias[col] : make_float2(0.f, 0.f);
        #pragma unroll
        for (int mt = 0; mt < 2; mt++) {
            size_t r0w = (size_t)(row0 + wm*32 + mt*16 + gid);
            float v0 = acc[mt][nt][0] + b2.x, v1 = acc[mt][nt][1] + b2.y;
            float v2 = acc[mt][nt][2] + b2.x, v3 = acc[mt][nt][3] + b2.y;
            if (dosilu) { v0 = silu(v0); v1 = silu(v1); v2 = silu(v2); v3 = silu(v3); }
            *(float2*)&OUT[r0w*96 + col]       = make_float2(v0, v1);
            *(float2*)&OUT[(r0w + 8)*96 + col] = make_float2(v2, v3);
        }
    }
    if (W2p) {
        __syncthreads();
        ACC_ZERO()
        mma_mainloop(AhS, AlS, BhS, BlS, wm, wn, lane, acc);
        #pragma unroll
        for (int nt = 0; nt < 6; nt++) {
            int col = wn*48 + nt*8 + tig*2;
            #pragma unroll
            for (int mt = 0; mt < 2; mt++) {
                size_t r0w = (size_t)(row0 + wm*32 + mt*16 + gid);
                *(float2*)&OUT2[r0w*96 + col]       = make_float2(acc[mt][nt][0], acc[mt][nt][1]);
                *(float2*)&OUT2[(r0w + 8)*96 + col] = make_float2(acc[mt][nt][2], acc[mt][nt][3]);
            }
        }
    }
}

// ---------------- fused node MLP: X = (silu(cat[X,A]@nw1+b1)) @ nw2 + b2 ----------------
__global__ __launch_bounds__(256, 2) void tnode_k(const float* __restrict__ Xin,
                                                  const float* __restrict__ Ain,
                                                  const float* __restrict__ W1,
                                                  const float* __restrict__ b1,
                                                  const float* __restrict__ W2,
                                                  const float* __restrict__ b2g,
                                                  float* __restrict__ Xout) {
    extern __shared__ __half smh[];
    __half* Ah = smh;
    __half* Al = Ah + 128*PK;
    __half* Bh = Al + 128*PK;
    __half* Bl = Bh + 96*PK;
    uint32_t AhS = smem_u32(Ah), AlS = smem_u32(Al), BhS = smem_u32(Bh), BlS = smem_u32(Bl);
    int tid = threadIdx.x;
    int warp = tid >> 5, lane = tid & 31;
    int gid = lane >> 2, tig = lane & 3;
    int wm = warp >> 1, wn = warp & 1;
    int row0 = blockIdx.x * 128;

    float acc[2][6][4];
    ACC_ZERO()
    for (int hh = 0; hh < 2; hh++) {
        const float* IN = hh ? Ain : Xin;
        const float* Wh = W1 + hh*96*96;
        TD_AFILL(IN)
        TD_BFILL(Wh)
        __syncthreads();
        mma_mainloop(AhS, AlS, BhS, BlS, wm, wn, lane, acc);
        __syncthreads();
    }
    // hoist W2 fill above the T-epilogue (B planes dead; overlaps LDG latency)
    TD_BFILL(W2)
    // T = silu(acc + b1) -> write into A planes (consumed by second GEMM)
    #pragma unroll
    for (int nt = 0; nt < 6; nt++) {
        int col = wn*48 + nt*8 + tig*2;
        float2 bb = *(const float2*)&b1[col];
        #pragma unroll
        for (int mt = 0; mt < 2; mt++) {
            int r = wm*32 + mt*16 + gid;
            float v0 = silu(acc[mt][nt][0] + bb.x), v1 = silu(acc[mt][nt][1] + bb.y);
            float v2 = silu(acc[mt][nt][2] + bb.x), v3 = silu(acc[mt][nt][3] + bb.y);
            uint32_t hi, lo;
            split2(v0, v1, hi, lo);
            *(uint32_t*)&Ah[r*PK + col] = hi;
            *(uint32_t*)&Al[r*PK + col] = lo;
            split2(v2, v3, hi, lo);
            *(uint32_t*)&Ah[(r+8)*PK + col] = hi;
            *(uint32_t*)&Al[(r+8)*PK + col] = lo;
        }
    }
    __syncthreads();
    ACC_ZERO()
    mma_mainloop(AhS, AlS, BhS, BlS, wm, wn, lane, acc);
    #pragma unroll
    for (int nt = 0; nt < 6; nt++) {
        int col = wn*48 + nt*8 + tig*2;
        float2 bb = *(const float2*)&b2g[col];
        #pragma unroll
        for (int mt = 0; mt < 2; mt++) {
            size_t r0w = (size_t)(row0 + wm*32 + mt*16 + gid);
            *(float2*)&Xout[r0w*96 + col] =
                make_float2(acc[mt][nt][0] + bb.x, acc[mt][nt][1] + bb.y);
            *(float2*)&Xout[(r0w + 8)*96 + col] =
                make_float2(acc[mt][nt][2] + bb.x, acc[mt][nt][3] + bb.y);
        }
    }
}

// ---------------- fused final: T = silu(X@dw1+db1) in smem; out += frame-mean decode ----------------
__global__ __launch_bounds__(256, 2) void tfinal_k(const float* __restrict__ Xin,
                                                   const float* __restrict__ W1,
                                                   const float* __restrict__ b1,
                                                   const float* __restrict__ dw2,
                                                   const float* __restrict__ db2,
                                                   float* __restrict__ out) {
    extern __shared__ __half smh[];
    __half* Ah = smh;
    __half* Al = Ah + 128*PK;
    __half* Bh = Al + 128*PK;
    __half* Bl = Bh + 96*PK;
    float*  Tsm = (float*)smh;           // [128][97] fp32, reuses A-plane region after GEMM
    uint32_t AhS = smem_u32(Ah), AlS = smem_u32(Al), BhS = smem_u32(Bh), BlS = smem_u32(Bl);
    __shared__ float dw2s[96*3];
    __shared__ float db2s[3];
    int tid = threadIdx.x;
    int warp = tid >> 5, lane = tid & 31;
    int gid = lane >> 2, tig = lane & 3;
    int wm = warp >> 1, wn = warp & 1;
    int row0 = blockIdx.x * 128;

    for (int i = tid; i < 96*3; i += 256) dw2s[i] = dw2[i];
    if (tid < 3) db2s[tid] = db2[tid];

    float acc[2][6][4];
    ACC_ZERO()
    TD_AFILL(Xin)
    TD_BFILL(W1)
    __syncthreads();
    mma_mainloop(AhS, AlS, BhS, BlS, wm, wn, lane, acc);
    __syncthreads();   // everyone done with A planes -> Tsm may overwrite
    #pragma unroll
    for (int nt = 0; nt < 6; nt++) {
        int col = wn*48 + nt*8 + tig*2;
        float2 bb = *(const float2*)&b1[col];
        #pragma unroll
        for (int mt = 0; mt < 2; mt++) {
            int r = wm*32 + mt*16 + gid;
            Tsm[r*97 + col]     = silu(acc[mt][nt][0] + bb.x);
            Tsm[r*97 + col + 1] = silu(acc[mt][nt][1] + bb.y);
            Tsm[(r+8)*97 + col]     = silu(acc[mt][nt][2] + bb.x);
            Tsm[(r+8)*97 + col + 1] = silu(acc[mt][nt][3] + bb.y);
        }
    }
    __syncthreads();
    if (tid < 128) {
        int grow = row0 + tid;
        int o = grow / NH;
        int node = grow - o*NH;
        int b = node / NN;
        const float* Tr = &Tsm[tid*97];
        float q0 = db2s[0], q1 = db2s[1], q2 = db2s[2];
        #pragma unroll 8
        for (int k = 0; k < 96; k++) {
            float t = Tr[k];
            q0 += t * dw2s[k*3+0];
            q1 += t * dw2s[k*3+1];
            q2 += t * dw2s[k*3+2];
        }
        float s0 = sgn(o,0)*q0, s1 = sgn(o,1)*q1, s2 = sgn(o,2)*q2;
        const float* V = &g_V[b*9];
        float v0 = V[0]*s0 + V[1]*s1 + V[2]*s2;
        float v1 = V[3]*s0 + V[4]*s1 + V[5]*s2;
        float v2 = V[6]*s0 + V[7]*s1 + V[8]*s2;
        atomicAdd(&out[(size_t)node*3 + 0], 0.125f*v0);
        atomicAdd(&out[(size_t)node*3 + 1], 0.125f*v1);
        atomicAdd(&out[(size_t)node*3 + 2], 0.125f*v2);
    }
}

// ---------------- edge kernel: EGPB graphs/block, 320 threads (10 warps: 5M x 2N) ----------------
#define EDGE_SMEM ((160*PK*2 + 96*PK*2)*2 + (192 + 96 + 2*EPG)*4)
__global__ __launch_bounds__(320, 2) void edge_k(const float* __restrict__ ea,
                                                 const float* __restrict__ Wea,
                                                 const float* __restrict__ eb1,
                                                 const float* __restrict__ W2,
                                                 const float* __restrict__ eb2) {
    extern __shared__ __half smh[];
    __half* M1h = smh;                    // [160][PK]
    __half* M1l = M1h + 160*PK;
    __half* Bh  = M1l + 160*PK;           // [96][PK]
    __half* Bl  = Bh + 96*PK;
    float*  Weas = (float*)(Bl + 96*PK);  // [192]
    float*  eb1s = Weas + 192;            // [96]
    float*  eas  = eb1s + 96;             // [40]
    uint32_t M1hS = smem_u32(M1h), M1lS = smem_u32(M1l);
    uint32_t BhS  = smem_u32(Bh),  BlS  = smem_u32(Bl);
    int tid = threadIdx.x;
    int warp = tid >> 5, lane = tid & 31;
    int gid = lane >> 2, tig = lane & 3;
    int wm = warp >> 1, wn = warp & 1;    // wm 0..4, wn 0..1

    for (int idx = tid; idx < 96*96; idx += 320) {
        int k = idx / 96, n = idx - k*96;
        float w = W2[idx];
        __half hv = __float2half_rn(w);
        float lv = w - __half2float(hv);
        Bh[n*PK + k] = hv;
        Bl[n*PK + k] = __float2half_rn(lv);
    }
    if (tid < 192) Weas[tid] = Wea[tid];
    if (tid >= 192 && tid < 288) eb1s[tid-192] = eb1[tid-192];
    if (tid >= 288 && tid < 288 + 2*EPG)
        eas[tid-288] = ea[(size_t)blockIdx.x*EGPB*EPG*2 + tid - 288];
    __syncthreads();

    for (int gg = 0; gg < EGPB; gg++) {
        int g = blockIdx.x * EGPB + gg;
        // m1 fill: 960 units (40 source-groups x 24 k-quads), 3 per thread
        #pragma unroll
        for (int t = 0; t < 3; t++) {
            int unit = tid + t*320;
            int m = unit / 24, q = unit - m*24;
            int u = m / 5, rr = m - u*5;
            size_t nb = (size_t)(u*NH + g*NN);
            float4 pr = *(const float4*)&g_PR[(nb+rr)*96 + q*4];
            float4 wa = *(const float4*)&Weas[q*4];
            float4 wb = *(const float4*)&Weas[96 + q*4];
            float4 be = *(const float4*)&eb1s[q*4];
            #pragma unroll
            for (int e = 0; e < 4; e++) {
                int c = e + (e >= rr);
                int le = rr*4 + e;
                float a0 = eas[le*2], a1 = eas[le*2+1];
                float4 pc = *(const float4*)&g_PC[(nb+c)*96 + q*4];
                float4 v;
                v.x = silu(pr.x + pc.x + a0*wa.x + a1*wb.x + be.x);
                v.y = silu(pr.y + pc.y + a0*wa.y + a1*wb.y + be.y);
                v.z = silu(pr.z + pc.z + a0*wa.z + a1*wb.z + be.z);
                v.w = silu(pr.w + pc.w + a0*wa.w + a1*wb.w + be.w);
                uint2 hi, lo;
                split4(v, hi, lo);
                int row = m*4 + e;
                *(uint2*)&M1h[row*PK + q*4] = hi;
                *(uint2*)&M1l[row*PK + q*4] = lo;
            }
        }
        __syncthreads();   // M1 ready; eas reads done

        if (gg + 1 < EGPB && tid < 2*EPG)
            eas[tid] = ea[(size_t)(g+1)*EPG*2 + tid];

        float acc[2][6][4];
        ACC_ZERO()
        mma_mainloop(M1hS, M1lS, BhS, BlS, wm, wn, lane, acc);

        // epilogue: silu + shuffle-aggregate 4 rows (lanes gid^1, gid^2) -> g_A
        #pragma unroll
        for (int nt = 0; nt < 6; nt++) {
            int col = wn*48 + nt*8 + tig*2;
            float2 b2 = *(const float2*)&eb2[col];
            #pragma unroll
            for (int mt = 0; mt < 2; mt++) {
                float v0 = silu(acc[mt][nt][0] + b2.x);
                float v1 = silu(acc[mt][nt][1] + b2.y);
                float v2 = silu(acc[mt][nt][2] + b2.x);
                float v3 = silu(acc[mt][nt][3] + b2.y);
                v0 += __shfl_xor_sync(0xffffffffu, v0, 4);
                v0 += __shfl_xor_sync(0xffffffffu, v0, 8);
                v1 += __shfl_xor_sync(0xffffffffu, v1, 4);
                v1 += __shfl_xor_sync(0xffffffffu, v1, 8);
                v2 += __shfl_xor_sync(0xffffffffu, v2, 4);
                v2 += __shfl_xor_sync(0xffffffffu, v2, 8);
                v3 += __shfl_xor_sync(0xffffffffu, v3, 4);
                v3 += __shfl_xor_sync(0xffffffffu, v3, 8);
                if ((gid & 3) == 0) {
                    int mlo = (wm*32 + mt*16 + gid) >> 2;
                    int mhi = mlo + 2;
                    int ulo = mlo / 5, rlo = mlo - ulo*5;
                    int uhi = mhi / 5, rhi = mhi - uhi*5;
                    *(float2*)&g_A[(size_t)(ulo*NH + g*NN + rlo)*96 + col] = make_float2(v0, v1);
                    *(float2*)&g_A[(size_t)(uhi*NH + g*NN + rhi)*96 + col] = make_float2(v2, v3);
                }
            }
        }
        __syncthreads();
    }
}

// ---------------- relatent: invert_latent + create_latent fused (block = graph) ----------------
__global__ __launch_bounds__(160) void relatent_kernel() {
    int b = blockIdx.x;
    int tid = threadIdx.x;
    int lane = tid & 31, warp = tid >> 5;
    int p = warp, f = lane;
    __shared__ float Vs[9];
    __shared__ float Vn[9];
    __shared__ float scen[3];
    __shared__ float wred[5][6];
    if (tid < 9) Vs[tid] = g_V[b*9 + tid];
    __syncthreads();
    float pm0 = 0.f, pm1 = 0.f, pm2 = 0.f;
    #pragma unroll
    for (int o = 0; o < NFR; o++) {
        const float* xr = &g_X[(size_t)(o*NH + b*NN + p)*HID + 3*f];
        float x0 = xr[0], x1 = xr[1], x2 = xr[2];
        float y0 = sgn(o,0)*x0, y1 = sgn(o,1)*x1, y2 = sgn(o,2)*x2;
        pm0 += Vs[0]*y0 + Vs[1]*y1 + Vs[2]*y2;
        pm1 += Vs[3]*y0 + Vs[4]*y1 + Vs[5]*y2;
        pm2 += Vs[6]*y0 + Vs[7]*y1 + Vs[8]*y2;
    }
    pm0 *= 0.125f; pm1 *= 0.125f; pm2 *= 0.125f;
    float r0 = pm0, r1 = pm1, r2 = pm2;
    for (int off = 16; off; off >>= 1) {
        r0 += __shfl_down_sync(0xffffffffu, r0, off);
        r1 += __shfl_down_sync(0xffffffffu, r1, off);
        r2 += __shfl_down_sync(0xffffffffu, r2, off);
    }
    if (lane == 0) { wred[warp][0]=r0; wred[warp][1]=r1; wred[warp][2]=r2; }
    __syncthreads();
    if (tid == 0) {
        float c0=0,c1=0,c2=0;
        for (int w = 0; w < 5; w++) { c0+=wred[w][0]; c1+=wred[w][1]; c2+=wred[w][2]; }
        scen[0] = c0/160.f; scen[1] = c1/160.f; scen[2] = c2/160.f;
    }
    __syncthreads();
    float d0 = pm0 - scen[0], d1 = pm1 - scen[1], d2 = pm2 - scen[2];
    float q[6] = { d0*d0, d0*d1, d0*d2, d1*d1, d1*d2, d2*d2 };
    #pragma unroll
    for (int i = 0; i < 6; i++) {
        float v = q[i];
        for (int off = 16; off; off >>= 1) v += __shfl_down_sync(0xffffffffu, v, off);
        q[i] = v;
    }
    if (lane == 0) { for (int i = 0; i < 6; i++) wred[warp][i] = q[i]; }
    __syncthreads();
    if (tid == 0) {
        double A[6] = {0,0,0,0,0,0};
        for (int w = 0; w < 5; w++)
            for (int i = 0; i < 6; i++) A[i] += (double)wred[w][i];
        float V[9];
        eigh3(A[0],A[1],A[2],A[3],A[4],A[5], V);
        for (int i = 0; i < 9; i++) { Vn[i] = V[i]; g_V[b*9+i] = V[i]; }
    }
    __syncthreads();
    float y0 = Vn[0]*d0 + Vn[3]*d1 + Vn[6]*d2;
    float y1 = Vn[1]*d0 + Vn[4]*d1 + Vn[7]*d2;
    float y2 = Vn[2]*d0 + Vn[5]*d1 + Vn[8]*d2;
    #pragma unroll
    for (int o = 0; o < NFR; o++) {
        float* xr = &g_X[(size_t)(o*NH + b*NN + p)*HID + 3*f];
        xr[0] = sgn(o,0)*y0; xr[1] = sgn(o,1)*y1; xr[2] = sgn(o,2)*y2;
    }
}

// ---------------- host launcher ----------------
extern "C" void kernel_launch(void* const* d_in, const int* in_sizes, int n_in,
                              void* d_out, int out_size) {
    const float* h     = (const float*)d_in[0];
    const float* ea    = (const float*)d_in[1];
    const float* emb_w = (const float*)d_in[2];
    const float* emb_b = (const float*)d_in[3];
    const float* ew1   = (const float*)d_in[4];   // [4,194,96]
    const float* eb1   = (const float*)d_in[5];   // [4,96]
    const float* ew2   = (const float*)d_in[6];   // [4,96,96]
    const float* eb2   = (const float*)d_in[7];   // [4,96]
    const float* nw1   = (const float*)d_in[8];   // [4,192,96]
    const float* nb1   = (const float*)d_in[9];
    const float* nw2   = (const float*)d_in[10];  // [4,96,96]
    const float* nb2   = (const float*)d_in[11];
    const float* dw1   = (const float*)d_in[12];  // [96,96]
    const float* db1   = (const float*)d_in[13];
    const float* dw2   = (const float*)d_in[14];  // [96,3]
    const float* db2   = (const float*)d_in[15];
    float* out = (float*)d_out;

    float *X, *A, *PR, *PC;
    cudaGetSymbolAddress((void**)&X,  g_X);
    cudaGetSymbolAddress((void**)&A,  g_A);
    cudaGetSymbolAddress((void**)&PR, g_PR);
    cudaGetSymbolAddress((void**)&PC, g_PC);
    cudaFuncSetAttribute(tdense_k, cudaFuncAttributeMaxDynamicSharedMemorySize, TD_SMEM);
    cudaFuncSetAttribute(tnode_k,  cudaFuncAttributeMaxDynamicSharedMemorySize, TD_SMEM);
    cudaFuncSetAttribute(tfinal_k, cudaFuncAttributeMaxDynamicSharedMemorySize, TD_SMEM);
    cudaFuncSetAttribute(edge_k,   cudaFuncAttributeMaxDynamicSharedMemorySize, EDGE_SMEM);

    frame_kernel<<<(BGR + 127)/128, 128>>>(h, out);
    embed_kernel<<<BGR*NFR, 96>>>(h, emb_w, emb_b);

    const int TG = RTOT / 128;   // 3125 tensor-dense blocks
    for (int l = 0; l < NL; l++) {
        const float* ew1_l = ew1 + (size_t)l*194*96;
        tdense_k<<<TG, 256, TD_SMEM>>>(X, nullptr, ew1_l, nullptr, PR, 1, 0,
                                       ew1_l + 96*96, PC);
        edge_k<<<BGR/EGPB, 320, EDGE_SMEM>>>(ea, ew1_l + 192*96, eb1 + l*96,
                                             ew2 + (size_t)l*96*96, eb2 + l*96);
        tnode_k<<<TG, 256, TD_SMEM>>>(X, A, nw1 + (size_t)l*192*96, nb1 + l*96,
                                      nw2 + (size_t)l*96*96, nb2 + l*96, X);
        if (l < NL - 1) relatent_kernel<<<BGR, 160>>>();
    }
    tfinal_k<<<TG, 256, TD_SMEM>>>(X, dw1, db1, dw2, db2, out);
}

// round 17
// speedup vs baseline: 1.0620x; 1.0115x over previous
#include <cuda_runtime.h>
#include <cuda_fp16.h>
#include <math.h>
#include <cstdint>

// ---------------- problem constants ----------------
#define BGR   10000          // graphs
#define NN    5              // nodes/graph
#define NFR   8              // frames
#define NH    (BGR*NN)       // 50000
#define RTOT  (NFR*NH)       // 400000 expanded rows
#define HID   96
#define EPG   20             // edges per graph
#define NL    4
#define EGPB  5              // graphs per edge block (wave-quantization fit: 7 waves x (C_f+5C_g))
#define PK    104            // smem pitch in halfs (conflict-free)

// ---------------- device scratch ----------------
__device__ float g_X [RTOT*HID];
__device__ float g_A [RTOT*HID];
__device__ float g_PR[RTOT*HID];
__device__ float g_PC[RTOT*HID];
__device__ float g_V [BGR*9];
__device__ float g_cen[BGR*3];

__device__ __forceinline__ float sgn(int o, int j) {
    return ((o >> (2 - j)) & 1) ? -1.f : 1.f;
}
// silu via single-MUFU tanh: x*sigmoid(x) = 0.5x + 0.5x*tanh(x/2)
__device__ __forceinline__ float silu(float v) {
    float h = 0.5f * v;
    float t;
    asm("tanh.approx.f32 %0, %1;" : "=f"(t) : "f"(h));
    return fmaf(h, t, h);
}
__device__ __forceinline__ uint32_t packh2(float x0, float x1) {
    uint32_t r;
    asm("cvt.rn.f16x2.f32 %0, %1, %2;" : "=r"(r) : "f"(x1), "f"(x0));
    return r;
}
__device__ __forceinline__ void split4(float4 v, uint2& hi, uint2& lo) {
    uint32_t h01 = packh2(v.x, v.y);
    uint32_t h23 = packh2(v.z, v.w);
    __half2 a = *(__half2*)&h01, b = *(__half2*)&h23;
    float2 fa = __half22float2(a), fb = __half22float2(b);
    lo.x = packh2(v.x - fa.x, v.y - fa.y);
    lo.y = packh2(v.z - fb.x, v.w - fb.y);
    hi.x = h01; hi.y = h23;
}
__device__ __forceinline__ void split2(float v0, float v1, uint32_t& hi, uint32_t& lo) {
    hi = packh2(v0, v1);
    __half2 a = *(__half2*)&hi;
    float2 f = __half22float2(a);
    lo = packh2(v0 - f.x, v1 - f.y);
}
__device__ __forceinline__ void mma16(float* c, const uint32_t* a, uint32_t b0, uint32_t b1) {
    asm volatile(
        "mma.sync.aligned.m16n8k16.row.col.f32.f16.f16.f32 "
        "{%0,%1,%2,%3}, {%4,%5,%6,%7}, {%8,%9}, {%0,%1,%2,%3};"
        : "+f"(c[0]), "+f"(c[1]), "+f"(c[2]), "+f"(c[3])
        : "r"(a[0]), "r"(a[1]), "r"(a[2]), "r"(a[3]), "r"(b0), "r"(b1));
}
__device__ __forceinline__ void ldmx4(uint32_t* r, uint32_t addr) {
    asm volatile("ldmatrix.sync.aligned.m8n8.x4.shared.b16 {%0,%1,%2,%3}, [%4];"
                 : "=r"(r[0]), "=r"(r[1]), "=r"(r[2]), "=r"(r[3]) : "r"(addr));
}
__device__ __forceinline__ uint32_t smem_u32(const void* p) {
    return (uint32_t)__cvta_generic_to_shared(p);
}

// fp16 2-split mainloop over K=96. Warp tile = 32M x 48N (wm rows, wn in {0,1}).
__device__ __forceinline__ void mma_mainloop(uint32_t AhS, uint32_t AlS,
                                             uint32_t BhS, uint32_t BlS,
                                             int wm, int wn, int lane,
                                             float acc[2][6][4]) {
    int aRow = lane & 15, aK = (lane >> 4) * 8;
    int bRow = lane & 7,  bK = ((lane >> 3) & 1) * 8;
    uint32_t bPlane = (lane >= 16) ? BlS : BhS;
    #pragma unroll
    for (int kt = 0; kt < 6; kt++) {
        int k0 = kt*16;
        uint32_t ah[2][4], al[2][4];
        #pragma unroll
        for (int mt = 0; mt < 2; mt++) {
            int rb = wm*32 + mt*16 + aRow;
            uint32_t off = (uint32_t)((rb*PK + aK + k0)*2);
            ldmx4(ah[mt], AhS + off);
            ldmx4(al[mt], AlS + off);
        }
        #pragma unroll
        for (int nt = 0; nt < 6; nt++) {
            int n0 = wn*48 + nt*8;
            uint32_t b4[4];
            ldmx4(b4, bPlane + (uint32_t)(((n0 + bRow)*PK + bK + k0)*2));
            #pragma unroll
            for (int mt = 0; mt < 2; mt++) {
                mma16(acc[mt][nt], ah[mt], b4[0], b4[1]);
                mma16(acc[mt][nt], ah[mt], b4[2], b4[3]);
                mma16(acc[mt][nt], al[mt], b4[0], b4[1]);
            }
        }
    }
}

// ---------------- 3x3 symmetric eigh (double, ascending columns) ----------------
__device__ inline void cross3d(const double* a, const double* b, double* c) {
    c[0] = a[1]*b[2] - a[2]*b[1];
    c[1] = a[2]*b[0] - a[0]*b[2];
    c[2] = a[0]*b[1] - a[1]*b[0];
}
__device__ inline void eigvec3(double a00,double a01,double a02,double a11,double a12,double a22,
                               double lam, double* v) {
    double r0[3] = {a00-lam, a01, a02};
    double r1[3] = {a01, a11-lam, a12};
    double r2[3] = {a02, a12, a22-lam};
    double c0[3], c1[3], c2[3];
    cross3d(r0, r1, c0); cross3d(r0, r2, c1); cross3d(r1, r2, c2);
    double n0 = c0[0]*c0[0]+c0[1]*c0[1]+c0[2]*c0[2];
    double n1 = c1[0]*c1[0]+c1[1]*c1[1]+c1[2]*c1[2];
    double n2 = c2[0]*c2[0]+c2[1]*c2[1]+c2[2]*c2[2];
    double* best = c0; double nb = n0;
    if (n1 > nb) { best = c1; nb = n1; }
    if (n2 > nb) { best = c2; nb = n2; }
    if (nb < 1e-300) { v[0]=1.0; v[1]=0.0; v[2]=0.0; return; }
    double inv = 1.0 / sqrt(nb);
    v[0] = best[0]*inv; v[1] = best[1]*inv; v[2] = best[2]*inv;
}
__device__ inline void eigh3(double a00,double a01,double a02,double a11,double a12,double a22,
                             float* V) {
    double p1 = a01*a01 + a02*a02 + a12*a12;
    double q  = (a00 + a11 + a22) / 3.0;
    double b00 = a00-q, b11 = a11-q, b22 = a22-q;
    double p2 = b00*b00 + b11*b11 + b22*b22 + 2.0*p1;
    if (p2 < 1e-60) {
        V[0]=1.f;V[1]=0.f;V[2]=0.f; V[3]=0.f;V[4]=1.f;V[5]=0.f; V[6]=0.f;V[7]=0.f;V[8]=1.f;
        return;
    }
    double p = sqrt(p2 / 6.0);
    double inv = 1.0 / p;
    double c00=b00*inv, c01=a01*inv, c02=a02*inv, c11=b11*inv, c12=a12*inv, c22=b22*inv;
    double det = c00*(c11*c22 - c12*c12) - c01*(c01*c22 - c12*c02) + c02*(c01*c12 - c11*c02);
    double r = 0.5 * det;
    r = fmin(1.0, fmax(-1.0, r));
    double phi  = acos(r) / 3.0;
    double lmax = q + 2.0*p*cos(phi);
    double lmin = q + 2.0*p*cos(phi + 2.0943951023931953);
    double vmin[3], vmax[3], vmid[3];
    eigvec3(a00,a01,a02,a11,a12,a22, lmin, vmin);
    eigvec3(a00,a01,a02,a11,a12,a22, lmax, vmax);
    cross3d(vmax, vmin, vmid);
    double nm = sqrt(vmid[0]*vmid[0]+vmid[1]*vmid[1]+vmid[2]*vmid[2]);
    double invm = (nm > 1e-300) ? 1.0/nm : 0.0;
    vmid[0]*=invm; vmid[1]*=invm; vmid[2]*=invm;
    V[0]=(float)vmin[0]; V[3]=(float)vmin[1]; V[6]=(float)vmin[2];
    V[1]=(float)vmid[0]; V[4]=(float)vmid[1]; V[7]=(float)vmid[2];
    V[2]=(float)vmax[0]; V[5]=(float)vmax[1]; V[8]=(float)vmax[2];
}

// ---------------- kernel: initial frames + out init (1 thread / graph) ----------------
__global__ void frame_kernel(const float* __restrict__ h, float* __restrict__ out) {
    int b = blockIdx.x * blockDim.x + threadIdx.x;
    if (b >= BGR) return;
    const float* hp = h + (size_t)(b*NN)*6;
    double P[NN][3];
    double c0=0, c1=0, c2=0;
    for (int p = 0; p < NN; p++) {
        P[p][0] = hp[p*6+0]; P[p][1] = hp[p*6+1]; P[p][2] = hp[p*6+2];
        c0 += P[p][0]; c1 += P[p][1]; c2 += P[p][2];
    }
    c0 *= 0.2; c1 *= 0.2; c2 *= 0.2;
    double a00=0,a01=0,a02=0,a11=0,a12=0,a22=0;
    for (int p = 0; p < NN; p++) {
        double d0 = P[p][0]-c0, d1 = P[p][1]-c1, d2 = P[p][2]-c2;
        a00 += d0*d0; a01 += d0*d1; a02 += d0*d2;
        a11 += d1*d1; a12 += d1*d2; a22 += d2*d2;
    }
    float V[9];
    eigh3(a00,a01,a02,a11,a12,a22, V);
    for (int i = 0; i < 9; i++) g_V[b*9+i] = V[i];
    g_cen[b*3+0] = (float)c0; g_cen[b*3+1] = (float)c1; g_cen[b*3+2] = (float)c2;
    for (int p = 0; p < NN; p++) {
        out[(size_t)(b*NN + p)*3 + 0] = (float)c0;
        out[(size_t)(b*NN + p)*3 + 1] = (float)c1;
        out[(size_t)(b*NN + p)*3 + 2] = (float)c2;
    }
}

// ---------------- kernel: frame transform + embedding (block = graph-frame) ----------------
__global__ __launch_bounds__(96) void embed_kernel(const float* __restrict__ h,
                                                   const float* __restrict__ Wg,
                                                   const float* __restrict__ bg) {
    int u = blockIdx.x;
    int g = u >> 3, o = u & 7;
    __shared__ float in6[NN][6];
    __shared__ float Vs[9];
    __shared__ float cen[3];
    int tid = threadIdx.x;
    if (tid < 9)  Vs[tid] = g_V[g*9+tid];
    if (tid >= 9 && tid < 12) cen[tid-9] = g_cen[g*3 + tid - 9];
    __syncthreads();
    if (tid < 30) {
        int p = tid / 6, k = tid - p*6;
        int i = k % 3; bool vel = (k >= 3);
        const float* hp = &h[(size_t)(g*NN + p)*6];
        float x0, x1, x2;
        if (vel) { x0 = hp[3]; x1 = hp[4]; x2 = hp[5]; }
        else     { x0 = hp[0]-cen[0]; x1 = hp[1]-cen[1]; x2 = hp[2]-cen[2]; }
        float val = Vs[0*3+i]*x0 + Vs[1*3+i]*x1 + Vs[2*3+i]*x2;
        in6[p][k] = sgn(o, i) * val;
    }
    __syncthreads();
    int j = tid;
    float bv = bg[j];
    for (int p = 0; p < NN; p++) {
        float s = bv;
        #pragma unroll
        for (int k = 0; k < 6; k++) s += in6[p][k] * Wg[k*96 + j];
        g_X[(size_t)(o*NH + g*NN + p)*HID + j] = s;
    }
}

// ---------------- tensor dense GEMM (single / dual weight), 256 threads ----------------
#define TD_SMEM ((128*PK*2 + 96*PK*2)*2)   // 93184 bytes
#define TD_BFILL(WSRC)                                                     \
    _Pragma("unroll")                                                      \
    for (int i = 0; i < 36; i++) {                                         \
        int idx = tid + i*256;                                             \
        int k = idx / 96, n = idx - k*96;                                  \
        float w = (WSRC)[idx];                                             \
        __half hv = __float2half_rn(w);                                    \
        float lv = w - __half2float(hv);                                   \
        Bh[n*PK + k] = hv;                                                 \
        Bl[n*PK + k] = __float2half_rn(lv);                                \
    }
#define TD_AFILL(INSRC)                                                    \
    _Pragma("unroll")                                                      \
    for (int i = 0; i < 12; i++) {                                         \
        int idx = tid + i*256;                                             \
        int r = idx / 24, q = idx - r*24;                                  \
        float4 v = *(const float4*)&(INSRC)[(size_t)(row0 + r)*96 + q*4];  \
        uint2 hi, lo;                                                      \
        split4(v, hi, lo);                                                 \
        *(uint2*)&Ah[r*PK + q*4] = hi;                                     \
        *(uint2*)&Al[r*PK + q*4] = lo;                                     \
    }
#define ACC_ZERO()                                                         \
    _Pragma("unroll")                                                      \
    for (int mt = 0; mt < 2; mt++)                                         \
        _Pragma("unroll")                                                  \
        for (int nt = 0; nt < 6; nt++)                                     \
            _Pragma("unroll")                                              \
            for (int e = 0; e < 4; e++) acc[mt][nt][e] = 0.f;

__global__ __launch_bounds__(256, 2) void tdense_k(const float* __restrict__ INa,
                                                   const float* __restrict__ INb,
                                                   const float* __restrict__ W,
                                                   const float* __restrict__ bias,
                                                   float* __restrict__ OUT,
                                                   int nhalves, int dosilu,
                                                   const float* __restrict__ W2p,
                                                   float* __restrict__ OUT2) {
    extern __shared__ __half smh[];
    __half* Ah = smh;
    __half* Al = Ah + 128*PK;
    __half* Bh = Al + 128*PK;
    __half* Bl = Bh + 96*PK;
    uint32_t AhS = smem_u32(Ah), AlS = smem_u32(Al), BhS = smem_u32(Bh), BlS = smem_u32(Bl);
    int tid = threadIdx.x;
    int warp = tid >> 5, lane = tid & 31;
    int gid = lane >> 2, tig = lane & 3;
    int wm = warp >> 1, wn = warp & 1;
    int row0 = blockIdx.x * 128;

    float acc[2][6][4];
    ACC_ZERO()
    for (int hh = 0; hh < nhalves; hh++) {
        const float* IN = hh ? INb : INa;
        const float* Wh = W + hh*96*96;
        TD_AFILL(IN)
        TD_BFILL(Wh)
        __syncthreads();
        mma_mainloop(AhS, AlS, BhS, BlS, wm, wn, lane, acc);
        __syncthreads();
    }
    // second-weight B fill hoisted above epilogue (B planes dead after mainloop;
    // LDG latency overlaps epilogue math + stores) — measured ~40us win round 15
    if (W2p) { TD_BFILL(W2p) }
    #pragma unroll
    for (int nt = 0; nt < 6; nt++) {
        int col = wn*48 + nt*8 + tig*2;
        float2 b2 = bias ? *(const float2*)&bias[col] : make_float2(0.f, 0.f);
        #pragma unroll
        for (int mt = 0; mt < 2; mt++) {
            size_t r0w = (size_t)(row0 + wm*32 + mt*16 + gid);
            float v0 = acc[mt][nt][0] + b2.x, v1 = acc[mt][nt][1] + b2.y;
            float v2 = acc[mt][nt][2] + b2.x, v3 = acc[mt][nt][3] + b2.y;
            if (dosilu) { v0 = silu(v0); v1 = silu(v1); v2 = silu(v2); v3 = silu(v3); }
            *(float2*)&OUT[r0w*96 + col]       = make_float2(v0, v1);
            *(float2*)&OUT[(r0w + 8)*96 + col] = make_float2(v2, v3);
        }
    }
    if (W2p) {
        __syncthreads();
        ACC_ZERO()
        mma_mainloop(AhS, AlS, BhS, BlS, wm, wn, lane, acc);
        #pragma unroll
        for (int nt = 0; nt < 6; nt++) {
            int col = wn*48 + nt*8 + tig*2;
            #pragma unroll
            for (int mt = 0; mt < 2; mt++) {
                size_t r0w = (size_t)(row0 + wm*32 + mt*16 + gid);
                *(float2*)&OUT2[r0w*96 + col]       = make_float2(acc[mt][nt][0], acc[mt][nt][1]);
                *(float2*)&OUT2[(r0w + 8)*96 + col] = make_float2(acc[mt][nt][2], acc[mt][nt][3]);
            }
        }
    }
}

// ---------------- fused node MLP: X = (silu(cat[X,A]@nw1+b1)) @ nw2 + b2 ----------------
__global__ __launch_bounds__(256, 2) void tnode_k(const float* __restrict__ Xin,
                                                  const float* __restrict__ Ain,
                                                  const float* __restrict__ W1,
                                                  const float* __restrict__ b1,
                                                  const float* __restrict__ W2,
                                                  const float* __restrict__ b2g,
                                                  float* __restrict__ Xout) {
    extern __shared__ __half smh[];
    __half* Ah = smh;
    __half* Al = Ah + 128*PK;
    __half* Bh = Al + 128*PK;
    __half* Bl = Bh + 96*PK;
    uint32_t AhS = smem_u32(Ah), AlS = smem_u32(Al), BhS = smem_u32(Bh), BlS = smem_u32(Bl);
    int tid = threadIdx.x;
    int warp = tid >> 5, lane = tid & 31;
    int gid = lane >> 2, tig = lane & 3;
    int wm = warp >> 1, wn = warp & 1;
    int row0 = blockIdx.x * 128;

    float acc[2][6][4];
    ACC_ZERO()
    for (int hh = 0; hh < 2; hh++) {
        const float* IN = hh ? Ain : Xin;
        const float* Wh = W1 + hh*96*96;
        TD_AFILL(IN)
        TD_BFILL(Wh)
        __syncthreads();
        mma_mainloop(AhS, AlS, BhS, BlS, wm, wn, lane, acc);
        __syncthreads();
    }
    // hoist W2 fill above the T-epilogue (B planes dead; overlaps LDG latency)
    TD_BFILL(W2)
    // T = silu(acc + b1) -> write into A planes (consumed by second GEMM)
    #pragma unroll
    for (int nt = 0; nt < 6; nt++) {
        int col = wn*48 + nt*8 + tig*2;
        float2 bb = *(const float2*)&b1[col];
        #pragma unroll
        for (int mt = 0; mt < 2; mt++) {
            int r = wm*32 + mt*16 + gid;
            float v0 = silu(acc[mt][nt][0] + bb.x), v1 = silu(acc[mt][nt][1] + bb.y);
            float v2 = silu(acc[mt][nt][2] + bb.x), v3 = silu(acc[mt][nt][3] + bb.y);
            uint32_t hi, lo;
            split2(v0, v1, hi, lo);
            *(uint32_t*)&Ah[r*PK + col] = hi;
            *(uint32_t*)&Al[r*PK + col] = lo;
            split2(v2, v3, hi, lo);
            *(uint32_t*)&Ah[(r+8)*PK + col] = hi;
            *(uint32_t*)&Al[(r+8)*PK + col] = lo;
        }
    }
    __syncthreads();
    ACC_ZERO()
    mma_mainloop(AhS, AlS, BhS, BlS, wm, wn, lane, acc);
    #pragma unroll
    for (int nt = 0; nt < 6; nt++) {
        int col = wn*48 + nt*8 + tig*2;
        float2 bb = *(const float2*)&b2g[col];
        #pragma unroll
        for (int mt = 0; mt < 2; mt++) {
            size_t r0w = (size_t)(row0 + wm*32 + mt*16 + gid);
            *(float2*)&Xout[r0w*96 + col] =
                make_float2(acc[mt][nt][0] + bb.x, acc[mt][nt][1] + bb.y);
            *(float2*)&Xout[(r0w + 8)*96 + col] =
                make_float2(acc[mt][nt][2] + bb.x, acc[mt][nt][3] + bb.y);
        }
    }
}

// ---------------- fused final: T = silu(X@dw1+db1) in smem; out += frame-mean decode ----------------
__global__ __launch_bounds__(256, 2) void tfinal_k(const float* __restrict__ Xin,
                                                   const float* __restrict__ W1,
                                                   const float* __restrict__ b1,
                                                   const float* __restrict__ dw2,
                                                   const float* __restrict__ db2,
                                                   float* __restrict__ out) {
    extern __shared__ __half smh[];
    __half* Ah = smh;
    __half* Al = Ah + 128*PK;
    __half* Bh = Al + 128*PK;
    __half* Bl = Bh + 96*PK;
    float*  Tsm = (float*)smh;           // [128][97] fp32, reuses A-plane region after GEMM
    uint32_t AhS = smem_u32(Ah), AlS = smem_u32(Al), BhS = smem_u32(Bh), BlS = smem_u32(Bl);
    __shared__ float dw2s[96*3];
    __shared__ float db2s[3];
    int tid = threadIdx.x;
    int warp = tid >> 5, lane = tid & 31;
    int gid = lane >> 2, tig = lane & 3;
    int wm = warp >> 1, wn = warp & 1;
    int row0 = blockIdx.x * 128;

    for (int i = tid; i < 96*3; i += 256) dw2s[i] = dw2[i];
    if (tid < 3) db2s[tid] = db2[tid];

    float acc[2][6][4];
    ACC_ZERO()
    TD_AFILL(Xin)
    TD_BFILL(W1)
    __syncthreads();
    mma_mainloop(AhS, AlS, BhS, BlS, wm, wn, lane, acc);
    __syncthreads();   // everyone done with A planes -> Tsm may overwrite
    #pragma unroll
    for (int nt = 0; nt < 6; nt++) {
        int col = wn*48 + nt*8 + tig*2;
        float2 bb = *(const float2*)&b1[col];
        #pragma unroll
        for (int mt = 0; mt < 2; mt++) {
            int r = wm*32 + mt*16 + gid;
            Tsm[r*97 + col]     = silu(acc[mt][nt][0] + bb.x);
            Tsm[r*97 + col + 1] = silu(acc[mt][nt][1] + bb.y);
            Tsm[(r+8)*97 + col]     = silu(acc[mt][nt][2] + bb.x);
            Tsm[(r+8)*97 + col + 1] = silu(acc[mt][nt][3] + bb.y);
        }
    }
    __syncthreads();
    if (tid < 128) {
        int grow = row0 + tid;
        int o = grow / NH;
        int node = grow - o*NH;
        int b = node / NN;
        const float* Tr = &Tsm[tid*97];
        float q0 = db2s[0], q1 = db2s[1], q2 = db2s[2];
        #pragma unroll 8
        for (int k = 0; k < 96; k++) {
            float t = Tr[k];
            q0 += t * dw2s[k*3+0];
            q1 += t * dw2s[k*3+1];
            q2 += t * dw2s[k*3+2];
        }
        float s0 = sgn(o,0)*q0, s1 = sgn(o,1)*q1, s2 = sgn(o,2)*q2;
        const float* V = &g_V[b*9];
        float v0 = V[0]*s0 + V[1]*s1 + V[2]*s2;
        float v1 = V[3]*s0 + V[4]*s1 + V[5]*s2;
        float v2 = V[6]*s0 + V[7]*s1 + V[8]*s2;
        atomicAdd(&out[(size_t)node*3 + 0], 0.125f*v0);
        atomicAdd(&out[(size_t)node*3 + 1], 0.125f*v1);
        atomicAdd(&out[(size_t)node*3 + 2], 0.125f*v2);
    }
}

// ---------------- edge kernel: EGPB graphs/block, 320 threads (10 warps: 5M x 2N) ----------------
#define EDGE_SMEM ((160*PK*2 + 96*PK*2)*2 + (192 + 96 + 2*EPG)*4)
__global__ __launch_bounds__(320, 2) void edge_k(const float* __restrict__ ea,
                                                 const float* __restrict__ Wea,
                                                 const float* __restrict__ eb1,
                                                 const float* __restrict__ W2,
                                                 const float* __restrict__ eb2) {
    extern __shared__ __half smh[];
    __half* M1h = smh;                    // [160][PK]
    __half* M1l = M1h + 160*PK;
    __half* Bh  = M1l + 160*PK;           // [96][PK]
    __half* Bl  = Bh + 96*PK;
    float*  Weas = (float*)(Bl + 96*PK);  // [192]
    float*  eb1s = Weas + 192;            // [96]
    float*  eas  = eb1s + 96;             // [40]
    uint32_t M1hS = smem_u32(M1h), M1lS = smem_u32(M1l);
    uint32_t BhS  = smem_u32(Bh),  BlS  = smem_u32(Bl);
    int tid = threadIdx.x;
    int warp = tid >> 5, lane = tid & 31;
    int gid = lane >> 2, tig = lane & 3;
    int wm = warp >> 1, wn = warp & 1;    // wm 0..4, wn 0..1

    for (int idx = tid; idx < 96*96; idx += 320) {
        int k = idx / 96, n = idx - k*96;
        float w = W2[idx];
        __half hv = __float2half_rn(w);
        float lv = w - __half2float(hv);
        Bh[n*PK + k] = hv;
        Bl[n*PK + k] = __float2half_rn(lv);
    }
    if (tid < 192) Weas[tid] = Wea[tid];
    if (tid >= 192 && tid < 288) eb1s[tid-192] = eb1[tid-192];
    if (tid >= 288 && tid < 288 + 2*EPG)
        eas[tid-288] = ea[(size_t)blockIdx.x*EGPB*EPG*2 + tid - 288];
    __syncthreads();

    for (int gg = 0; gg < EGPB; gg++) {
        int g = blockIdx.x * EGPB + gg;
        // m1 fill: 960 units (40 source-groups x 24 k-quads), 3 per thread
        #pragma unroll
        for (int t = 0; t < 3; t++) {
            int unit = tid + t*320;
            int m = unit / 24, q = unit - m*24;
            int u = m / 5, rr = m - u*5;
            size_t nb = (size_t)(u*NH + g*NN);
            float4 pr = *(const float4*)&g_PR[(nb+rr)*96 + q*4];
            float4 wa = *(const float4*)&Weas[q*4];
            float4 wb = *(const float4*)&Weas[96 + q*4];
            float4 be = *(const float4*)&eb1s[q*4];
            #pragma unroll
            for (int e = 0; e < 4; e++) {
                int c = e + (e >= rr);
                int le = rr*4 + e;
                float a0 = eas[le*2], a1 = eas[le*2+1];
                float4 pc = *(const float4*)&g_PC[(nb+c)*96 + q*4];
                float4 v;
                v.x = silu(pr.x + pc.x + a0*wa.x + a1*wb.x + be.x);
                v.y = silu(pr.y + pc.y + a0*wa.y + a1*wb.y + be.y);
                v.z = silu(pr.z + pc.z + a0*wa.z + a1*wb.z + be.z);
                v.w = silu(pr.w + pc.w + a0*wa.w + a1*wb.w + be.w);
                uint2 hi, lo;
                split4(v, hi, lo);
                int row = m*4 + e;
                *(uint2*)&M1h[row*PK + q*4] = hi;
                *(uint2*)&M1l[row*PK + q*4] = lo;
            }
        }
        __syncthreads();   // M1 ready; eas reads done

        if (gg + 1 < EGPB && tid < 2*EPG)
            eas[tid] = ea[(size_t)(g+1)*EPG*2 + tid];

        float acc[2][6][4];
        ACC_ZERO()
        mma_mainloop(M1hS, M1lS, BhS, BlS, wm, wn, lane, acc);

        // epilogue: silu + shuffle-aggregate 4 rows (lanes gid^1, gid^2) -> g_A
        #pragma unroll
        for (int nt = 0; nt < 6; nt++) {
            int col = wn*48 + nt*8 + tig*2;
            float2 b2 = *(const float2*)&eb2[col];
            #pragma unroll
            for (int mt = 0; mt < 2; mt++) {
                float v0 = silu(acc[mt][nt][0] + b2.x);
                float v1 = silu(acc[mt][nt][1] + b2.y);
                float v2 = silu(acc[mt][nt][2] + b2.x);
                float v3 = silu(acc[mt][nt][3] + b2.y);
                v0 += __shfl_xor_sync(0xffffffffu, v0, 4);
                v0 += __shfl_xor_sync(0xffffffffu, v0, 8);
                v1 += __shfl_xor_sync(0xffffffffu, v1, 4);
                v1 += __shfl_xor_sync(0xffffffffu, v1, 8);
                v2 += __shfl_xor_sync(0xffffffffu, v2, 4);
                v2 += __shfl_xor_sync(0xffffffffu, v2, 8);
                v3 += __shfl_xor_sync(0xffffffffu, v3, 4);
                v3 += __shfl_xor_sync(0xffffffffu, v3, 8);
                if ((gid & 3) == 0) {
                    int mlo = (wm*32 + mt*16 + gid) >> 2;
                    int mhi = mlo + 2;
                    int ulo = mlo / 5, rlo = mlo - ulo*5;
                    int uhi = mhi / 5, rhi = mhi - uhi*5;
                    *(float2*)&g_A[(size_t)(ulo*NH + g*NN + rlo)*96 + col] = make_float2(v0, v1);
                    *(float2*)&g_A[(size_t)(uhi*NH + g*NN + rhi)*96 + col] = make_float2(v2, v3);
                }
            }
        }
        __syncthreads();
    }
}

// ---------------- relatent: invert_latent + create_latent fused (block = graph) ----------------
__global__ __launch_bounds__(160) void relatent_kernel() {
    int b = blockIdx.x;
    int tid = threadIdx.x;
    int lane = tid & 31, warp = tid >> 5;
    int p = warp, f = lane;
    __shared__ float Vs[9];
    __shared__ float Vn[9];
    __shared__ float scen[3];
    __shared__ float wred[5][6];
    if (tid < 9) Vs[tid] = g_V[b*9 + tid];
    __syncthreads();
    float pm0 = 0.f, pm1 = 0.f, pm2 = 0.f;
    #pragma unroll
    for (int o = 0; o < NFR; o++) {
        const float* xr = &g_X[(size_t)(o*NH + b*NN + p)*HID + 3*f];
        float x0 = xr[0], x1 = xr[1], x2 = xr[2];
        float y0 = sgn(o,0)*x0, y1 = sgn(o,1)*x1, y2 = sgn(o,2)*x2;
        pm0 += Vs[0]*y0 + Vs[1]*y1 + Vs[2]*y2;
        pm1 += Vs[3]*y0 + Vs[4]*y1 + Vs[5]*y2;
        pm2 += Vs[6]*y0 + Vs[7]*y1 + Vs[8]*y2;
    }
    pm0 *= 0.125f; pm1 *= 0.125f; pm2 *= 0.125f;
    float r0 = pm0, r1 = pm1, r2 = pm2;
    for (int off = 16; off; off >>= 1) {
        r0 += __shfl_down_sync(0xffffffffu, r0, off);
        r1 += __shfl_down_sync(0xffffffffu, r1, off);
        r2 += __shfl_down_sync(0xffffffffu, r2, off);
    }
    if (lane == 0) { wred[warp][0]=r0; wred[warp][1]=r1; wred[warp][2]=r2; }
    __syncthreads();
    if (tid == 0) {
        float c0=0,c1=0,c2=0;
        for (int w = 0; w < 5; w++) { c0+=wred[w][0]; c1+=wred[w][1]; c2+=wred[w][2]; }
        scen[0] = c0/160.f; scen[1] = c1/160.f; scen[2] = c2/160.f;
    }
    __syncthreads();
    float d0 = pm0 - scen[0], d1 = pm1 - scen[1], d2 = pm2 - scen[2];
    float q[6] = { d0*d0, d0*d1, d0*d2, d1*d1, d1*d2, d2*d2 };
    #pragma unroll
    for (int i = 0; i < 6; i++) {
        float v = q[i];
        for (int off = 16; off; off >>= 1) v += __shfl_down_sync(0xffffffffu, v, off);
        q[i] = v;
    }
    if (lane == 0) { for (int i = 0; i < 6; i++) wred[warp][i] = q[i]; }
    __syncthreads();
    if (tid == 0) {
        double A[6] = {0,0,0,0,0,0};
        for (int w = 0; w < 5; w++)
            for (int i = 0; i < 6; i++) A[i] += (double)wred[w][i];
        float V[9];
        eigh3(A[0],A[1],A[2],A[3],A[4],A[5], V);
        for (int i = 0; i < 9; i++) { Vn[i] = V[i]; g_V[b*9+i] = V[i]; }
    }
    __syncthreads();
    float y0 = Vn[0]*d0 + Vn[3]*d1 + Vn[6]*d2;
    float y1 = Vn[1]*d0 + Vn[4]*d1 + Vn[7]*d2;
    float y2 = Vn[2]*d0 + Vn[5]*d1 + Vn[8]*d2;
    #pragma unroll
    for (int o = 0; o < NFR; o++) {
        float* xr = &g_X[(size_t)(o*NH + b*NN + p)*HID + 3*f];
        xr[0] = sgn(o,0)*y0; xr[1] = sgn(o,1)*y1; xr[2] = sgn(o,2)*y2;
    }
}

// ---------------- host launcher ----------------
extern "C" void kernel_launch(void* const* d_in, const int* in_sizes, int n_in,
                              void* d_out, int out_size) {
    const float* h     = (const float*)d_in[0];
    const float* ea    = (const float*)d_in[1];
    const float* emb_w = (const float*)d_in[2];
    const float* emb_b = (const float*)d_in[3];
    const float* ew1   = (const float*)d_in[4];   // [4,194,96]
    const float* eb1   = (const float*)d_in[5];   // [4,96]
    const float* ew2   = (const float*)d_in[6];   // [4,96,96]
    const float* eb2   = (const float*)d_in[7];   // [4,96]
    const float* nw1   = (const float*)d_in[8];   // [4,192,96]
    const float* nb1   = (const float*)d_in[9];
    const float* nw2   = (const float*)d_in[10];  // [4,96,96]
    const float* nb2   = (const float*)d_in[11];
    const float* dw1   = (const float*)d_in[12];  // [96,96]
    const float* db1   = (const float*)d_in[13];
    const float* dw2   = (const float*)d_in[14];  // [96,3]
    const float* db2   = (const float*)d_in[15];
    float* out = (float*)d_out;

    float *X, *A, *PR, *PC;
    cudaGetSymbolAddress((void**)&X,  g_X);
    cudaGetSymbolAddress((void**)&A,  g_A);
    cudaGetSymbolAddress((void**)&PR, g_PR);
    cudaGetSymbolAddress((void**)&PC, g_PC);
    cudaFuncSetAttribute(tdense_k, cudaFuncAttributeMaxDynamicSharedMemorySize, TD_SMEM);
    cudaFuncSetAttribute(tnode_k,  cudaFuncAttributeMaxDynamicSharedMemorySize, TD_SMEM);
    cudaFuncSetAttribute(tfinal_k, cudaFuncAttributeMaxDynamicSharedMemorySize, TD_SMEM);
    cudaFuncSetAttribute(edge_k,   cudaFuncAttributeMaxDynamicSharedMemorySize, EDGE_SMEM);

    frame_kernel<<<(BGR + 127)/128, 128>>>(h, out);
    embed_kernel<<<BGR*NFR, 96>>>(h, emb_w, emb_b);

    const int TG = RTOT / 128;   // 3125 tensor-dense blocks
    for (int l = 0; l < NL; l++) {
        const float* ew1_l = ew1 + (size_t)l*194*96;
        tdense_k<<<TG, 256, TD_SMEM>>>(X, nullptr, ew1_l, nullptr, PR, 1, 0,
                                       ew1_l + 96*96, PC);
        edge_k<<<BGR/EGPB, 320, EDGE_SMEM>>>(ea, ew1_l + 192*96, eb1 + l*96,
                                             ew2 + (size_t)l*96*96, eb2 + l*96);
        tnode_k<<<TG, 256, TD_SMEM>>>(X, A, nw1 + (size_t)l*192*96, nb1 + l*96,
                                      nw2 + (size_t)l*96*96, nb2 + l*96, X);
        if (l < NL - 1) relatent_kernel<<<BGR, 160>>>();
    }
    tfinal_k<<<TG, 256, TD_SMEM>>>(X, dw1, db1, dw2, db2, out);
}